// round 7
// baseline (speedup 1.0000x reference)
#include <cuda_runtime.h>
#include <math.h>
#include <stdint.h>
#include <string.h>

#define BB 64
#define SS 40
#define TD 39
#define EE 256
#define UU 1024
#define VV 8192
#define G3 3072

// Scratch (device globals; no allocation allowed)
static __device__ float g_gxe[BB * SS * G3];      // encoder x@Wx + b0
static __device__ float g_gxd[BB * TD * G3];      // decoder xt@Wx_bot + b0
static __device__ float g_enc_out[BB * SS * UU];  // encoder hidden sequence
static __device__ float g_P[BB * SS * G3];        // enc_out @ dec_Wx[:U]
static __device__ float g_hdec[BB * TD * UU];     // decoder hidden per step
static __device__ unsigned g_bar[2];              // [0]=count, [1]=release epoch

// ---------------------------------------------------------------------------
// packed fp32x2 FMA (2x FFMA pipe throughput on sm_103a)
// ---------------------------------------------------------------------------
__device__ __forceinline__ float2 fma2(float2 a, float2 b, float2 c) {
    unsigned long long ua, ub, uc;
    memcpy(&ua, &a, 8); memcpy(&ub, &b, 8); memcpy(&uc, &c, 8);
    asm("fma.rn.f32x2 %0, %1, %2, %0;" : "+l"(uc) : "l"(ua), "l"(ub));
    float2 r; memcpy(&r, &uc, 8);
    return r;
}

__device__ __forceinline__ float sigmoidf_(float x) {
    return 1.0f / (1.0f + expf(-x));
}

// ---------------------------------------------------------------------------
// fp32 GEMM v3:  C[M,N] = A[M,K] @ W[K,N] (+ bias)
// Optional row gather: A row m = emb[idx[(m/TT)*stride + m%TT]]
// 128x128 block tile, BK=8, 256 threads, 8x8 microtile, col-packed f32x2.
// Software pipeline: double-buffered smem stages; LDGs for tile i+1 issued
// before computing tile i (latency hidden). One __syncthreads per iteration.
// N multiple of 128; K multiple of 8; M arbitrary (clamped loads, guarded
// stores).
// ---------------------------------------------------------------------------
__global__ __launch_bounds__(256, 2) void gemm_f32(
    const float* __restrict__ A,
    const float* __restrict__ emb, const int* __restrict__ idx,
    int idxTT, int idxStride, int lda,
    const float* __restrict__ W, int ldw,
    const float* __restrict__ bias,
    float* __restrict__ C, int M, int N, int K)
{
    __shared__ __align__(16) float As[2][8][128];
    __shared__ __align__(16) float Ws[2][8][128];

    const int tid = threadIdx.x;
    const int bm = blockIdx.y * 128;
    const int bn = blockIdx.x * 128;

    // A loader: row = bm + (tid&127), 4 consecutive k at offset 4*(tid>>7)
    const int arow_l = tid & 127;
    const int akh    = tid >> 7;       // 0..1 -> k offset 0 / 4
    int mload = bm + arow_l;
    if (mload >= M) mload = M - 1;     // clamp (store side is guarded)
    const float* arow;
    if (emb) {
        int r = idx[(mload / idxTT) * idxStride + (mload % idxTT)];
        arow = emb + (size_t)r * lda;
    } else {
        arow = A + (size_t)mload * lda;
    }

    // W loader: k row tid>>5 (0..7), 4 cols at (tid&31)*4
    const int wk = tid >> 5;
    const int wn = (tid & 31) * 4;
    const float* wptr = W + (size_t)wk * ldw + bn + wn;

    const int tx = tid & 15, ty = tid >> 4;
    const int r0 = ty * 8, c0 = tx * 8;

    float2 acc[8][4];
#pragma unroll
    for (int r = 0; r < 8; r++)
#pragma unroll
        for (int c = 0; c < 4; c++) acc[r][c] = make_float2(0.f, 0.f);

    const int nIter = K >> 3;

    // Prologue: load tile 0 and stage it
    float4 av = *reinterpret_cast<const float4*>(arow + akh * 4);
    float4 wv = *reinterpret_cast<const float4*>(wptr);
    As[0][akh * 4 + 0][arow_l] = av.x;
    As[0][akh * 4 + 1][arow_l] = av.y;
    As[0][akh * 4 + 2][arow_l] = av.z;
    As[0][akh * 4 + 3][arow_l] = av.w;
    *reinterpret_cast<float4*>(&Ws[0][wk][wn]) = wv;
    __syncthreads();

    for (int it = 0; it < nIter; it++) {
        const int cur = it & 1;
        // Issue next tile's loads (latency overlapped with compute below)
        if (it + 1 < nIter) {
            av = *reinterpret_cast<const float4*>(arow + (it + 1) * 8 + akh * 4);
            wv = *reinterpret_cast<const float4*>(wptr + (size_t)(it + 1) * 8 * ldw);
        }
        // Compute 8 k on current stage
#pragma unroll
        for (int k = 0; k < 8; k++) {
            float4 a0 = *reinterpret_cast<const float4*>(&As[cur][k][r0]);
            float4 a1 = *reinterpret_cast<const float4*>(&As[cur][k][r0 + 4]);
            float4 w0 = *reinterpret_cast<const float4*>(&Ws[cur][k][c0]);
            float4 w1 = *reinterpret_cast<const float4*>(&Ws[cur][k][c0 + 4]);
            float2 w[4];
            w[0] = make_float2(w0.x, w0.y);
            w[1] = make_float2(w0.z, w0.w);
            w[2] = make_float2(w1.x, w1.y);
            w[3] = make_float2(w1.z, w1.w);
            float ar[8] = {a0.x, a0.y, a0.z, a0.w, a1.x, a1.y, a1.z, a1.w};
#pragma unroll
            for (int r = 0; r < 8; r++) {
                float2 ad = make_float2(ar[r], ar[r]);
#pragma unroll
                for (int c = 0; c < 4; c++)
                    acc[r][c] = fma2(ad, w[c], acc[r][c]);
            }
        }
        // Stage next tile into the other buffer
        if (it + 1 < nIter) {
            const int nxt = cur ^ 1;
            As[nxt][akh * 4 + 0][arow_l] = av.x;
            As[nxt][akh * 4 + 1][arow_l] = av.y;
            As[nxt][akh * 4 + 2][arow_l] = av.z;
            As[nxt][akh * 4 + 3][arow_l] = av.w;
            *reinterpret_cast<float4*>(&Ws[nxt][wk][wn]) = wv;
            __syncthreads();
        }
    }

    // Epilogue: 8 rows x 8 cols per thread, 2x STG.128 per row
    float bv[8];
#pragma unroll
    for (int j = 0; j < 8; j++) bv[j] = bias ? bias[bn + c0 + j] : 0.f;
#pragma unroll
    for (int r = 0; r < 8; r++) {
        int mrow = bm + r0 + r;
        if (mrow < M) {
            float4 o0, o1;
            o0.x = acc[r][0].x + bv[0];
            o0.y = acc[r][0].y + bv[1];
            o0.z = acc[r][1].x + bv[2];
            o0.w = acc[r][1].y + bv[3];
            o1.x = acc[r][2].x + bv[4];
            o1.y = acc[r][2].y + bv[5];
            o1.z = acc[r][3].x + bv[6];
            o1.w = acc[r][3].y + bv[7];
            *reinterpret_cast<float4*>(C + (size_t)mrow * N + bn + c0)     = o0;
            *reinterpret_cast<float4*>(C + (size_t)mrow * N + bn + c0 + 4) = o1;
        }
    }
}

// ---------------------------------------------------------------------------
// Persistent encoder recurrence. ONE launch for all 40 steps.
// grid = 128 blocks x 128 threads; block bi owns u in [bi*8, bi*8+8)
// (24 output cols = 3 gates x 8). Wh slice (96KB) cached in shared once.
// Grid barrier between steps via global atomic counter + release epoch.
// NOTE: all shared strides EVEN so float2 LDS/STS.64 stay 8B-aligned.
// ---------------------------------------------------------------------------
#define ENC_BLOCKS 128
#define ENC_THREADS 128
#define WSH_FLOATS (1024 * 24)
#define HST_STRIDE 66
#define HST_BUF (32 * HST_STRIDE)
#define GHS_STRIDE 26
#define ENC_SMEM_FLOATS (WSH_FLOATS + 2 * HST_BUF + 64 * GHS_STRIDE)
#define ENC_SMEM_BYTES (ENC_SMEM_FLOATS * 4)

__global__ __launch_bounds__(ENC_THREADS, 1) void enc_persistent(
    const float* __restrict__ gxe,   // [B*S][3U]  (includes b0)
    const float* __restrict__ Wh,    // [U][3U]
    const float* __restrict__ b1,    // [3U]
    float* __restrict__ enc_out,     // [B*S][U]
    unsigned* bar_cnt, unsigned* bar_rel)
{
    extern __shared__ float sm[];
    float* Wsh  = sm;                              // [1024][24]
    float* hst  = sm + WSH_FLOATS;                 // [2][32][HST_STRIDE]
    float* ghsh = sm + WSH_FLOATS + 2 * HST_BUF;   // [64][GHS_STRIDE]

    const int tid = threadIdx.x;
    const int bi  = blockIdx.x;
    const int u0  = bi * 8;

    // Preload this block's Wh slice: Wsh[k][gate*8+du] = Wh[k][gate*1024+u0+du]
    for (int i = tid; i < WSH_FLOATS; i += ENC_THREADS) {
        int k = i / 24, c = i % 24;
        Wsh[i] = Wh[(size_t)k * G3 + (c >> 3) * UU + u0 + (c & 7)];
    }

    __shared__ unsigned relbase_s;
    if (tid == 0) relbase_s = *(volatile unsigned*)bar_rel;
    __syncthreads();
    const unsigned relbase = relbase_s;

    const int rg = tid >> 2;          // 0..31: rows 2rg, 2rg+1
    const int cg = tid & 3;           // col-pair group: cpairs cg*3..cg*3+2

    for (int t = 0; t < SS; t++) {
        if (t > 0) {
            // ---- grid barrier #t: wait until all blocks wrote h_{t-1} ----
            __threadfence();
            __syncthreads();
            if (tid == 0) {
                unsigned old = atomicAdd(bar_cnt, 1u);
                if (old == ENC_BLOCKS - 1) {
                    atomicExch(bar_cnt, 0u);
                    __threadfence();
                    atomicAdd(bar_rel, 1u);
                }
                while (*(volatile unsigned*)bar_rel - relbase < (unsigned)t) {}
            }
            __syncthreads();
            __threadfence();
        }

        float2 acc[2][3];
#pragma unroll
        for (int p = 0; p < 2; p++)
#pragma unroll
            for (int j = 0; j < 3; j++) acc[p][j] = make_float2(0.f, 0.f);

        if (t > 0) {
            const float* hprev = enc_out + (size_t)(t - 1) * UU;  // + b*SS*UU

            float4 pf[4];
            // prefetch chunk 0
#pragma unroll
            for (int q = 0; q < 4; q++) {
                int e = q * 128 + tid;
                int row = e >> 3, k4 = e & 7;
                pf[q] = *reinterpret_cast<const float4*>(
                    hprev + (size_t)row * (SS * UU) + k4 * 4);
            }
#pragma unroll
            for (int q = 0; q < 4; q++) {
                int e = q * 128 + tid;
                int row = e >> 3, k4 = e & 7;
                hst[(k4 * 4 + 0) * HST_STRIDE + row] = pf[q].x;
                hst[(k4 * 4 + 1) * HST_STRIDE + row] = pf[q].y;
                hst[(k4 * 4 + 2) * HST_STRIDE + row] = pf[q].z;
                hst[(k4 * 4 + 3) * HST_STRIDE + row] = pf[q].w;
            }
            __syncthreads();

            for (int c = 0; c < 32; c++) {
                if (c + 1 < 32) {
#pragma unroll
                    for (int q = 0; q < 4; q++) {
                        int e = q * 128 + tid;
                        int row = e >> 3, k4 = e & 7;
                        pf[q] = *reinterpret_cast<const float4*>(
                            hprev + (size_t)row * (SS * UU) + (c + 1) * 32 + k4 * 4);
                    }
                }
                const float* hb = hst + (c & 1) * HST_BUF;
                const float* wb = Wsh + (size_t)c * 32 * 24 + cg * 6;
#pragma unroll
                for (int kk = 0; kk < 32; kk++) {
                    float2 hp = *reinterpret_cast<const float2*>(hb + kk * HST_STRIDE + rg * 2);
                    float2 d0 = make_float2(hp.x, hp.x);
                    float2 d1 = make_float2(hp.y, hp.y);
                    const float* wr = wb + kk * 24;
                    float2 w0 = *reinterpret_cast<const float2*>(wr + 0);
                    float2 w1 = *reinterpret_cast<const float2*>(wr + 2);
                    float2 w2 = *reinterpret_cast<const float2*>(wr + 4);
                    acc[0][0] = fma2(d0, w0, acc[0][0]);
                    acc[1][0] = fma2(d1, w0, acc[1][0]);
                    acc[0][1] = fma2(d0, w1, acc[0][1]);
                    acc[1][1] = fma2(d1, w1, acc[1][1]);
                    acc[0][2] = fma2(d0, w2, acc[0][2]);
                    acc[1][2] = fma2(d1, w2, acc[1][2]);
                }
                if (c + 1 < 32) {
                    float* dst = hst + ((c + 1) & 1) * HST_BUF;
#pragma unroll
                    for (int q = 0; q < 4; q++) {
                        int e = q * 128 + tid;
                        int row = e >> 3, k4 = e & 7;
                        dst[(k4 * 4 + 0) * HST_STRIDE + row] = pf[q].x;
                        dst[(k4 * 4 + 1) * HST_STRIDE + row] = pf[q].y;
                        dst[(k4 * 4 + 2) * HST_STRIDE + row] = pf[q].z;
                        dst[(k4 * 4 + 3) * HST_STRIDE + row] = pf[q].w;
                    }
                    __syncthreads();
                }
            }

            // scatter gh to shared for epilogue regrouping
            __syncthreads();
#pragma unroll
            for (int j = 0; j < 3; j++) {
                int cp = cg * 3 + j;
                *reinterpret_cast<float2*>(ghsh + (2 * rg) * GHS_STRIDE + 2 * cp)     = acc[0][j];
                *reinterpret_cast<float2*>(ghsh + (2 * rg + 1) * GHS_STRIDE + 2 * cp) = acc[1][j];
            }
            __syncthreads();
        }

        // Epilogue: 4 (b,u) outputs per thread
        {
            int b = tid >> 1;
            const float* gxrow = gxe + (size_t)(b * SS + t) * G3;
#pragma unroll
            for (int j = 0; j < 4; j++) {
                int du = (tid & 1) * 4 + j;
                int u = u0 + du;
                float ghz = 0.f, ghr = 0.f, ghc = 0.f, hold = 0.f;
                if (t > 0) {
                    ghz = ghsh[b * GHS_STRIDE + du];
                    ghr = ghsh[b * GHS_STRIDE + 8 + du];
                    ghc = ghsh[b * GHS_STRIDE + 16 + du];
                    hold = enc_out[(size_t)(b * SS + t - 1) * UU + u];
                }
                float z = sigmoidf_(gxrow[u] + ghz + b1[u]);
                float r = sigmoidf_(gxrow[UU + u] + ghr + b1[UU + u]);
                float cc = tanhf(gxrow[2 * UU + u] + r * (ghc + b1[2 * UU + u]));
                enc_out[(size_t)(b * SS + t) * UU + u] = z * hold + (1.f - z) * cc;
            }
        }
    }
}

// ---------------------------------------------------------------------------
// Decoder step (one block per batch b, 256 threads):
//   scores = h . enc_out ; softmax ; gx_ctx = sum_s w_s * P[b,s,:] ; GRU(h0=0)
// ---------------------------------------------------------------------------
__global__ __launch_bounds__(256) void dec_step_kernel(
    const float* __restrict__ h_prev, int hp_stride,
    const float* __restrict__ enc_out,
    const float* __restrict__ P,
    const float* __restrict__ gxd_t, int gxd_stride,
    const float* __restrict__ db1,
    float* __restrict__ h_out, int ho_stride)
{
    const int b = blockIdx.x;
    const int tid = threadIdx.x;
    const int warp = tid >> 5, lane = tid & 31;

    __shared__ float wsm[SS];
    __shared__ float gxc[G3];

    {
        const float* hb = h_prev + (size_t)b * hp_stride;
        const float* eb = enc_out + (size_t)b * SS * UU;
        float acc[5] = {0.f, 0.f, 0.f, 0.f, 0.f};
#pragma unroll 4
        for (int i = 0; i < 32; i++) {
            int uidx = lane + 32 * i;
            float hv = hb[uidx];
#pragma unroll
            for (int q = 0; q < 5; q++)
                acc[q] += hv * eb[(size_t)(warp * 5 + q) * UU + uidx];
        }
#pragma unroll
        for (int q = 0; q < 5; q++) {
            float v = acc[q];
            for (int o = 16; o; o >>= 1) v += __shfl_xor_sync(0xffffffffu, v, o);
            if (lane == 0) wsm[warp * 5 + q] = v;
        }
    }
    __syncthreads();

    if (tid == 0) {
        float mx = -1e30f;
        for (int s = 0; s < SS; s++) mx = fmaxf(mx, wsm[s]);
        float sm = 0.f;
        for (int s = 0; s < SS; s++) { float e = expf(wsm[s] - mx); wsm[s] = e; sm += e; }
        float inv = 1.f / sm;
        for (int s = 0; s < SS; s++) wsm[s] *= inv;
    }
    __syncthreads();

    {
        const float* Pb = P + (size_t)b * SS * G3;
        float a[12];
#pragma unroll
        for (int i = 0; i < 12; i++) a[i] = 0.f;
        for (int s = 0; s < SS; s++) {
            float w = wsm[s];
            const float* row = Pb + (size_t)s * G3;
#pragma unroll
            for (int i = 0; i < 12; i++)
                a[i] += w * row[tid + i * 256];
        }
#pragma unroll
        for (int i = 0; i < 12; i++) gxc[tid + i * 256] = a[i];
    }
    __syncthreads();

    {
        const float* gx = gxd_t + (size_t)b * gxd_stride;
        float* ho = h_out + (size_t)b * ho_stride;
#pragma unroll
        for (int i = 0; i < 4; i++) {
            int u = tid + i * 256;
            float z = sigmoidf_(gxc[u] + gx[u] + db1[u]);
            float r = sigmoidf_(gxc[UU + u] + gx[UU + u] + db1[UU + u]);
            float c = tanhf(gxc[2 * UU + u] + gx[2 * UU + u] + r * db1[2 * UU + u]);
            ho[u] = (1.f - z) * c;
        }
    }
}

// ---------------------------------------------------------------------------
extern "C" void kernel_launch(void* const* d_in, const int* in_sizes, int n_in,
                              void* d_out, int out_size)
{
    const int*   inp     = (const int*)d_in[0];
    const int*   targ    = (const int*)d_in[1];
    const float* enc_emb = (const float*)d_in[2];
    const float* enc_Wx  = (const float*)d_in[3];
    const float* enc_Wh  = (const float*)d_in[4];
    const float* enc_b   = (const float*)d_in[5];
    const float* dec_emb = (const float*)d_in[6];
    const float* dec_Wx  = (const float*)d_in[7];
    // d_in[8] = dec_Wh: provably unused (decoder GRU hidden input is zeros)
    const float* dec_b   = (const float*)d_in[9];
    const float* fc_W    = (const float*)d_in[10];
    const float* fc_b    = (const float*)d_in[11];
    float* out = (float*)d_out;

    float *gxe, *gxd, *enc_out, *P, *hdec;
    unsigned* bar;
    cudaGetSymbolAddress((void**)&gxe,     g_gxe);
    cudaGetSymbolAddress((void**)&gxd,     g_gxd);
    cudaGetSymbolAddress((void**)&enc_out, g_enc_out);
    cudaGetSymbolAddress((void**)&P,       g_P);
    cudaGetSymbolAddress((void**)&hdec,    g_hdec);
    cudaGetSymbolAddress((void**)&bar,     g_bar);

    cudaFuncSetAttribute(enc_persistent,
                         cudaFuncAttributeMaxDynamicSharedMemorySize, ENC_SMEM_BYTES);

    // 1) Encoder gx for all timesteps: (B*S,3U) = emb[inp] @ enc_Wx + b0
    gemm_f32<<<dim3(G3 / 128, (BB * SS + 127) / 128), 256>>>(
        nullptr, enc_emb, inp, SS, SS, EE,
        enc_Wx, G3, enc_b, gxe, BB * SS, G3, EE);

    // 2) Decoder xt-part gx for all steps: emb[targ[:, :-1]] @ dec_Wx[U:] + b0
    gemm_f32<<<dim3(G3 / 128, (BB * TD + 127) / 128), 256>>>(
        nullptr, dec_emb, targ, TD, SS, EE,
        dec_Wx + (size_t)UU * G3, G3, dec_b, gxd, BB * TD, G3, EE);

    // 3) Encoder recurrence: ONE persistent kernel with grid barriers
    enc_persistent<<<ENC_BLOCKS, ENC_THREADS, ENC_SMEM_BYTES>>>(
        gxe, enc_Wh, enc_b + G3, enc_out, bar, bar + 1);

    // 4) P = enc_out @ dec_Wx[:U]   (factored attention-context projection)
    gemm_f32<<<dim3(G3 / 128, (BB * SS + 127) / 128), 256>>>(
        enc_out, nullptr, nullptr, 1, 1, UU,
        dec_Wx, G3, nullptr, P, BB * SS, G3, UU);

    // 5) Decoder recurrence (sequential, cheap: attention + weighted sum + GRU)
    for (int t = 0; t < TD; t++) {
        const float* hp;
        int hps;
        if (t == 0) { hp = enc_out + (size_t)(SS - 1) * UU; hps = SS * UU; }
        else        { hp = hdec + (size_t)(t - 1) * UU;     hps = TD * UU; }
        dec_step_kernel<<<BB, 256>>>(
            hp, hps, enc_out, P,
            gxd + (size_t)t * G3, TD * G3,
            dec_b + G3,
            hdec + (size_t)t * UU, TD * UU);
    }

    // 6) Batched output projection: preds = hdec @ fc_W + fc_b
    gemm_f32<<<dim3(VV / 128, (BB * TD + 127) / 128), 256>>>(
        hdec, nullptr, nullptr, 1, 1, UU,
        fc_W, VV, fc_b, out, BB * TD, VV, UU);
}

// round 8
// speedup vs baseline: 1.3024x; 1.3024x over previous
#include <cuda_runtime.h>
#include <math.h>
#include <stdint.h>
#include <string.h>

#define BB 64
#define SS 40
#define TD 39
#define EE 256
#define UU 1024
#define VV 8192
#define G3 3072

// Scratch (device globals; no allocation allowed)
static __device__ float g_gxe[BB * SS * G3];      // encoder x@Wx + b0
static __device__ float g_gxd[BB * TD * G3];      // decoder xt@Wx_bot + b0
static __device__ float g_enc_out[BB * SS * UU];  // encoder hidden sequence
static __device__ float g_P[BB * SS * G3];        // enc_out @ dec_Wx[:U]
static __device__ float g_hdec[BB * TD * UU];     // decoder hidden per step
static __device__ unsigned g_bar[2];              // [0]=count, [1]=release epoch

// ---------------------------------------------------------------------------
// packed fp32x2 FMA (2x FFMA pipe throughput on sm_103a)
// ---------------------------------------------------------------------------
__device__ __forceinline__ float2 fma2(float2 a, float2 b, float2 c) {
    unsigned long long ua, ub, uc;
    memcpy(&ua, &a, 8); memcpy(&ub, &b, 8); memcpy(&uc, &c, 8);
    asm("fma.rn.f32x2 %0, %1, %2, %0;" : "+l"(uc) : "l"(ua), "l"(ub));
    float2 r; memcpy(&r, &uc, 8);
    return r;
}

__device__ __forceinline__ float sigmoidf_(float x) {
    return 1.0f / (1.0f + expf(-x));
}

__device__ __forceinline__ uint32_t f2tf32(float x) {
    uint32_t r;
    asm("cvt.rna.tf32.f32 %0, %1;" : "=r"(r) : "f"(x));
    return r;
}

__device__ __forceinline__ void mma_tf32(float c[4], const uint32_t a[4],
                                         const uint32_t b[2]) {
    asm("mma.sync.aligned.m16n8k8.row.col.f32.tf32.tf32.f32 "
        "{%0,%1,%2,%3},{%4,%5,%6,%7},{%8,%9},{%0,%1,%2,%3};"
        : "+f"(c[0]), "+f"(c[1]), "+f"(c[2]), "+f"(c[3])
        : "r"(a[0]), "r"(a[1]), "r"(a[2]), "r"(a[3]), "r"(b[0]), "r"(b[1]));
}

// ---------------------------------------------------------------------------
// fp32 GEMM (scalar f32x2 path) — used only where fp32 accuracy is required
// upstream of the encoder recurrence (step 1).
// 128x128 block tile, BK=8, 256 threads, 8x8 microtile.
// ---------------------------------------------------------------------------
__global__ __launch_bounds__(256, 2) void gemm_f32(
    const float* __restrict__ A,
    const float* __restrict__ emb, const int* __restrict__ idx,
    int idxTT, int idxStride, int lda,
    const float* __restrict__ W, int ldw,
    const float* __restrict__ bias,
    float* __restrict__ C, int M, int N, int K)
{
    __shared__ __align__(16) float As[2][8][128];
    __shared__ __align__(16) float Ws[2][8][128];

    const int tid = threadIdx.x;
    const int bm = blockIdx.y * 128;
    const int bn = blockIdx.x * 128;

    const int arow_l = tid & 127;
    const int akh    = tid >> 7;
    int mload = bm + arow_l;
    if (mload >= M) mload = M - 1;
    const float* arow;
    if (emb) {
        int r = idx[(mload / idxTT) * idxStride + (mload % idxTT)];
        arow = emb + (size_t)r * lda;
    } else {
        arow = A + (size_t)mload * lda;
    }

    const int wk = tid >> 5;
    const int wn = (tid & 31) * 4;
    const float* wptr = W + (size_t)wk * ldw + bn + wn;

    const int tx = tid & 15, ty = tid >> 4;
    const int r0 = ty * 8, c0 = tx * 8;

    float2 acc[8][4];
#pragma unroll
    for (int r = 0; r < 8; r++)
#pragma unroll
        for (int c = 0; c < 4; c++) acc[r][c] = make_float2(0.f, 0.f);

    const int nIter = K >> 3;

    float4 av = *reinterpret_cast<const float4*>(arow + akh * 4);
    float4 wv = *reinterpret_cast<const float4*>(wptr);
    As[0][akh * 4 + 0][arow_l] = av.x;
    As[0][akh * 4 + 1][arow_l] = av.y;
    As[0][akh * 4 + 2][arow_l] = av.z;
    As[0][akh * 4 + 3][arow_l] = av.w;
    *reinterpret_cast<float4*>(&Ws[0][wk][wn]) = wv;
    __syncthreads();

    for (int it = 0; it < nIter; it++) {
        const int cur = it & 1;
        if (it + 1 < nIter) {
            av = *reinterpret_cast<const float4*>(arow + (it + 1) * 8 + akh * 4);
            wv = *reinterpret_cast<const float4*>(wptr + (size_t)(it + 1) * 8 * ldw);
        }
#pragma unroll
        for (int k = 0; k < 8; k++) {
            float4 a0 = *reinterpret_cast<const float4*>(&As[cur][k][r0]);
            float4 a1 = *reinterpret_cast<const float4*>(&As[cur][k][r0 + 4]);
            float4 w0 = *reinterpret_cast<const float4*>(&Ws[cur][k][c0]);
            float4 w1 = *reinterpret_cast<const float4*>(&Ws[cur][k][c0 + 4]);
            float2 w[4];
            w[0] = make_float2(w0.x, w0.y);
            w[1] = make_float2(w0.z, w0.w);
            w[2] = make_float2(w1.x, w1.y);
            w[3] = make_float2(w1.z, w1.w);
            float ar[8] = {a0.x, a0.y, a0.z, a0.w, a1.x, a1.y, a1.z, a1.w};
#pragma unroll
            for (int r = 0; r < 8; r++) {
                float2 ad = make_float2(ar[r], ar[r]);
#pragma unroll
                for (int c = 0; c < 4; c++)
                    acc[r][c] = fma2(ad, w[c], acc[r][c]);
            }
        }
        if (it + 1 < nIter) {
            const int nxt = cur ^ 1;
            As[nxt][akh * 4 + 0][arow_l] = av.x;
            As[nxt][akh * 4 + 1][arow_l] = av.y;
            As[nxt][akh * 4 + 2][arow_l] = av.z;
            As[nxt][akh * 4 + 3][arow_l] = av.w;
            *reinterpret_cast<float4*>(&Ws[nxt][wk][wn]) = wv;
            __syncthreads();
        }
    }

    float bv[8];
#pragma unroll
    for (int j = 0; j < 8; j++) bv[j] = bias ? bias[bn + c0 + j] : 0.f;
#pragma unroll
    for (int r = 0; r < 8; r++) {
        int mrow = bm + r0 + r;
        if (mrow < M) {
            float4 o0, o1;
            o0.x = acc[r][0].x + bv[0];
            o0.y = acc[r][0].y + bv[1];
            o0.z = acc[r][1].x + bv[2];
            o0.w = acc[r][1].y + bv[3];
            o1.x = acc[r][2].x + bv[4];
            o1.y = acc[r][2].y + bv[5];
            o1.z = acc[r][3].x + bv[6];
            o1.w = acc[r][3].y + bv[7];
            *reinterpret_cast<float4*>(C + (size_t)mrow * N + bn + c0)     = o0;
            *reinterpret_cast<float4*>(C + (size_t)mrow * N + bn + c0 + 4) = o1;
        }
    }
}

// ---------------------------------------------------------------------------
// tf32 tensor-core GEMM: C[M,N] = A[M,K] @ W[K,N] (+ bias), via
// mma.sync.m16n8k8 (HMMA). Used for GEMMs NOT feeding the encoder
// recurrence (tf32 rounding ~4e-4 RMS does not compound there).
// 128x128 block, BK=16, 256 threads = 8 warps (4m x 2n), warp tile 32x64.
// smem strides 136 => conflict-free fragment LDS. Double-buffered.
// N mult of 128; K mult of 16; M arbitrary.
// ---------------------------------------------------------------------------
#define TFS 136

__global__ __launch_bounds__(256) void gemm_tf32(
    const float* __restrict__ A,
    const float* __restrict__ emb, const int* __restrict__ idx,
    int idxTT, int idxStride, int lda,
    const float* __restrict__ W, int ldw,
    const float* __restrict__ bias,
    float* __restrict__ C, int M, int N, int K)
{
    __shared__ __align__(16) uint32_t Ast[2][16][TFS];  // [k][row]
    __shared__ __align__(16) uint32_t Bst[2][16][TFS];  // [k][col]

    const int tid  = threadIdx.x;
    const int lane = tid & 31;
    const int wid  = tid >> 5;
    const int wm   = wid & 3;         // m-slice: rows wm*32..wm*32+31
    const int wn   = wid >> 2;        // n-half: cols wn*64..wn*64+63
    const int g    = lane >> 2;       // group id 0..7
    const int qt   = lane & 3;        // thread-in-group 0..3

    const int bm = blockIdx.y * 128;
    const int bn = blockIdx.x * 128;

    // A loader: row = tid&127, k-range kh*8..kh*8+7
    const int arow_l = tid & 127;
    const int akh    = tid >> 7;
    int mload = bm + arow_l;
    if (mload >= M) mload = M - 1;
    const float* arow;
    if (emb) {
        int r = idx[(mload / idxTT) * idxStride + (mload % idxTT)];
        arow = emb + (size_t)r * lda;
    } else {
        arow = A + (size_t)mload * lda;
    }

    // W loader: k rows wk, wk+8; 4 cols at (tid&31)*4
    const int wk  = tid >> 5;
    const int wn4 = (tid & 31) * 4;
    const float* wptr = W + (size_t)wk * ldw + bn + wn4;

    float acc[2][8][4];
#pragma unroll
    for (int mf = 0; mf < 2; mf++)
#pragma unroll
        for (int nf = 0; nf < 8; nf++)
#pragma unroll
            for (int q = 0; q < 4; q++) acc[mf][nf][q] = 0.f;

    const int nIter = K >> 4;

    float4 av0 = *reinterpret_cast<const float4*>(arow + akh * 8);
    float4 av1 = *reinterpret_cast<const float4*>(arow + akh * 8 + 4);
    float4 wv0 = *reinterpret_cast<const float4*>(wptr);
    float4 wv1 = *reinterpret_cast<const float4*>(wptr + (size_t)8 * ldw);
    {
        const float a0[8] = {av0.x, av0.y, av0.z, av0.w, av1.x, av1.y, av1.z, av1.w};
#pragma unroll
        for (int j = 0; j < 8; j++) Ast[0][akh * 8 + j][arow_l] = f2tf32(a0[j]);
        uint4 p0 = make_uint4(f2tf32(wv0.x), f2tf32(wv0.y), f2tf32(wv0.z), f2tf32(wv0.w));
        uint4 p1 = make_uint4(f2tf32(wv1.x), f2tf32(wv1.y), f2tf32(wv1.z), f2tf32(wv1.w));
        *reinterpret_cast<uint4*>(&Bst[0][wk][wn4])     = p0;
        *reinterpret_cast<uint4*>(&Bst[0][wk + 8][wn4]) = p1;
    }
    __syncthreads();

    for (int it = 0; it < nIter; it++) {
        const int cur = it & 1;
        if (it + 1 < nIter) {
            av0 = *reinterpret_cast<const float4*>(arow + (it + 1) * 16 + akh * 8);
            av1 = *reinterpret_cast<const float4*>(arow + (it + 1) * 16 + akh * 8 + 4);
            wv0 = *reinterpret_cast<const float4*>(wptr + (size_t)(it + 1) * 16 * ldw);
            wv1 = *reinterpret_cast<const float4*>(wptr + (size_t)((it + 1) * 16 + 8) * ldw);
        }
#pragma unroll
        for (int k8 = 0; k8 < 2; k8++) {
            uint32_t afrag[2][4];
#pragma unroll
            for (int mf = 0; mf < 2; mf++) {
                int R = wm * 32 + mf * 16;
                afrag[mf][0] = Ast[cur][k8 * 8 + qt][R + g];
                afrag[mf][1] = Ast[cur][k8 * 8 + qt][R + g + 8];
                afrag[mf][2] = Ast[cur][k8 * 8 + qt + 4][R + g];
                afrag[mf][3] = Ast[cur][k8 * 8 + qt + 4][R + g + 8];
            }
#pragma unroll
            for (int nf = 0; nf < 8; nf++) {
                uint32_t bfrag[2];
                int cidx = wn * 64 + nf * 8 + g;
                bfrag[0] = Bst[cur][k8 * 8 + qt][cidx];
                bfrag[1] = Bst[cur][k8 * 8 + qt + 4][cidx];
                mma_tf32(acc[0][nf], afrag[0], bfrag);
                mma_tf32(acc[1][nf], afrag[1], bfrag);
            }
        }
        if (it + 1 < nIter) {
            const int nxt = cur ^ 1;
            const float a0[8] = {av0.x, av0.y, av0.z, av0.w, av1.x, av1.y, av1.z, av1.w};
#pragma unroll
            for (int j = 0; j < 8; j++) Ast[nxt][akh * 8 + j][arow_l] = f2tf32(a0[j]);
            uint4 p0 = make_uint4(f2tf32(wv0.x), f2tf32(wv0.y), f2tf32(wv0.z), f2tf32(wv0.w));
            uint4 p1 = make_uint4(f2tf32(wv1.x), f2tf32(wv1.y), f2tf32(wv1.z), f2tf32(wv1.w));
            *reinterpret_cast<uint4*>(&Bst[nxt][wk][wn4])     = p0;
            *reinterpret_cast<uint4*>(&Bst[nxt][wk + 8][wn4]) = p1;
            __syncthreads();
        }
    }

    // Epilogue: c0,c1 -> (row g, cols qt*2, qt*2+1); c2,c3 -> row g+8
#pragma unroll
    for (int nf = 0; nf < 8; nf++) {
        int colb = bn + wn * 64 + nf * 8 + qt * 2;
        float b0 = bias ? bias[colb]     : 0.f;
        float b1 = bias ? bias[colb + 1] : 0.f;
#pragma unroll
        for (int mf = 0; mf < 2; mf++) {
            int row0 = bm + wm * 32 + mf * 16 + g;
            if (row0 < M) {
                float2 v = make_float2(acc[mf][nf][0] + b0, acc[mf][nf][1] + b1);
                *reinterpret_cast<float2*>(C + (size_t)row0 * N + colb) = v;
            }
            int row1 = row0 + 8;
            if (row1 < M) {
                float2 v = make_float2(acc[mf][nf][2] + b0, acc[mf][nf][3] + b1);
                *reinterpret_cast<float2*>(C + (size_t)row1 * N + colb) = v;
            }
        }
    }
}

// ---------------------------------------------------------------------------
// Persistent encoder recurrence v2. ONE launch for all 40 steps.
// 128 blocks x 256 threads; block bi owns u in [bi*8, bi*8+8).
// k-SPLIT: warps 0-3 handle k in [0,512), warps 4-7 handle [512,1024),
// partial gh reduced through shared memory -> 2 warps/SMSP for latency hiding.
// Wh slice (96KB) cached in shared once. Grid barrier between steps.
// ---------------------------------------------------------------------------
#define ENC_BLOCKS 128
#define ENC_THREADS 256
#define WSH_FLOATS (1024 * 24)
#define HST_STRIDE 66
#define HST_BUF (32 * HST_STRIDE)
#define GHS_STRIDE 26
#define ENC_SMEM_FLOATS (WSH_FLOATS + 4 * HST_BUF + 2 * 64 * GHS_STRIDE)
#define ENC_SMEM_BYTES (ENC_SMEM_FLOATS * 4)

__global__ __launch_bounds__(ENC_THREADS, 1) void enc_persistent(
    const float* __restrict__ gxe,   // [B*S][3U]  (includes b0)
    const float* __restrict__ Wh,    // [U][3U]
    const float* __restrict__ b1,    // [3U]
    float* __restrict__ enc_out,     // [B*S][U]
    unsigned* bar_cnt, unsigned* bar_rel)
{
    extern __shared__ float sm[];
    float* Wsh  = sm;                               // [1024][24]
    float* hstA = sm + WSH_FLOATS;                  // half-local [2][32][66]
    float* ghsh = sm + WSH_FLOATS + 4 * HST_BUF;    // [2][64][26]

    const int tid   = threadIdx.x;
    const int khalf = tid >> 7;          // 0 or 1: k range half
    const int ltid  = tid & 127;
    const int bi    = blockIdx.x;
    const int u0    = bi * 8;

    float* hst = hstA + khalf * 2 * HST_BUF;
    float* ghw = ghsh + khalf * 64 * GHS_STRIDE;

    // Preload this block's Wh slice: Wsh[k][gate*8+du]
    for (int i = tid; i < WSH_FLOATS; i += ENC_THREADS) {
        int k = i / 24, c = i % 24;
        Wsh[i] = Wh[(size_t)k * G3 + (c >> 3) * UU + u0 + (c & 7)];
    }

    __shared__ unsigned relbase_s;
    if (tid == 0) relbase_s = *(volatile unsigned*)bar_rel;
    __syncthreads();
    const unsigned relbase = relbase_s;

    const int rg = ltid >> 2;         // 0..31: rows 2rg, 2rg+1
    const int cg = ltid & 3;          // col-pair group: cpairs cg*3..cg*3+2

    for (int t = 0; t < SS; t++) {
        if (t > 0) {
            __threadfence();
            __syncthreads();
            if (tid == 0) {
                unsigned old = atomicAdd(bar_cnt, 1u);
                if (old == ENC_BLOCKS - 1) {
                    atomicExch(bar_cnt, 0u);
                    __threadfence();
                    atomicAdd(bar_rel, 1u);
                }
                while (*(volatile unsigned*)bar_rel - relbase < (unsigned)t) {}
            }
            __syncthreads();
            __threadfence();
        }

        float2 acc[2][3];
#pragma unroll
        for (int p = 0; p < 2; p++)
#pragma unroll
            for (int j = 0; j < 3; j++) acc[p][j] = make_float2(0.f, 0.f);

        if (t > 0) {
            const float* hprev = enc_out + (size_t)(t - 1) * UU + khalf * 512;

            float4 pf[4];
#pragma unroll
            for (int q = 0; q < 4; q++) {
                int e = q * 128 + ltid;
                int row = e >> 3, k4 = e & 7;
                pf[q] = *reinterpret_cast<const float4*>(
                    hprev + (size_t)row * (SS * UU) + k4 * 4);
            }
#pragma unroll
            for (int q = 0; q < 4; q++) {
                int e = q * 128 + ltid;
                int row = e >> 3, k4 = e & 7;
                hst[(k4 * 4 + 0) * HST_STRIDE + row] = pf[q].x;
                hst[(k4 * 4 + 1) * HST_STRIDE + row] = pf[q].y;
                hst[(k4 * 4 + 2) * HST_STRIDE + row] = pf[q].z;
                hst[(k4 * 4 + 3) * HST_STRIDE + row] = pf[q].w;
            }
            __syncthreads();

            for (int c = 0; c < 16; c++) {
                if (c + 1 < 16) {
#pragma unroll
                    for (int q = 0; q < 4; q++) {
                        int e = q * 128 + ltid;
                        int row = e >> 3, k4 = e & 7;
                        pf[q] = *reinterpret_cast<const float4*>(
                            hprev + (size_t)row * (SS * UU) + (c + 1) * 32 + k4 * 4);
                    }
                }
                const float* hb = hst + (c & 1) * HST_BUF;
                const float* wb = Wsh + (size_t)(khalf * 16 + c) * 32 * 24 + cg * 6;
#pragma unroll
                for (int kk = 0; kk < 32; kk++) {
                    float2 hp = *reinterpret_cast<const float2*>(hb + kk * HST_STRIDE + rg * 2);
                    float2 d0 = make_float2(hp.x, hp.x);
                    float2 d1 = make_float2(hp.y, hp.y);
                    const float* wr = wb + kk * 24;
                    float2 w0 = *reinterpret_cast<const float2*>(wr + 0);
                    float2 w1 = *reinterpret_cast<const float2*>(wr + 2);
                    float2 w2 = *reinterpret_cast<const float2*>(wr + 4);
                    acc[0][0] = fma2(d0, w0, acc[0][0]);
                    acc[1][0] = fma2(d1, w0, acc[1][0]);
                    acc[0][1] = fma2(d0, w1, acc[0][1]);
                    acc[1][1] = fma2(d1, w1, acc[1][1]);
                    acc[0][2] = fma2(d0, w2, acc[0][2]);
                    acc[1][2] = fma2(d1, w2, acc[1][2]);
                }
                if (c + 1 < 16) {
                    float* dst = hst + ((c + 1) & 1) * HST_BUF;
#pragma unroll
                    for (int q = 0; q < 4; q++) {
                        int e = q * 128 + ltid;
                        int row = e >> 3, k4 = e & 7;
                        dst[(k4 * 4 + 0) * HST_STRIDE + row] = pf[q].x;
                        dst[(k4 * 4 + 1) * HST_STRIDE + row] = pf[q].y;
                        dst[(k4 * 4 + 2) * HST_STRIDE + row] = pf[q].z;
                        dst[(k4 * 4 + 3) * HST_STRIDE + row] = pf[q].w;
                    }
                    __syncthreads();
                }
            }

            // scatter partial gh to this half's buffer
            __syncthreads();
#pragma unroll
            for (int j = 0; j < 3; j++) {
                int cp = cg * 3 + j;
                *reinterpret_cast<float2*>(ghw + (2 * rg) * GHS_STRIDE + 2 * cp)     = acc[0][j];
                *reinterpret_cast<float2*>(ghw + (2 * rg + 1) * GHS_STRIDE + 2 * cp) = acc[1][j];
            }
            __syncthreads();
        }

        // Epilogue: 2 (b,u) outputs per thread (256 threads, 512 outputs)
        {
            int b = tid >> 2;
            const float* gxrow = gxe + (size_t)(b * SS + t) * G3;
            const float* gh0 = ghsh + b * GHS_STRIDE;
            const float* gh1 = ghsh + 64 * GHS_STRIDE + b * GHS_STRIDE;
#pragma unroll
            for (int j = 0; j < 2; j++) {
                int du = (tid & 3) * 2 + j;
                int u = u0 + du;
                float ghz = 0.f, ghr = 0.f, ghc = 0.f, hold = 0.f;
                if (t > 0) {
                    ghz = gh0[du]      + gh1[du];
                    ghr = gh0[8 + du]  + gh1[8 + du];
                    ghc = gh0[16 + du] + gh1[16 + du];
                    hold = enc_out[(size_t)(b * SS + t - 1) * UU + u];
                }
                float z = sigmoidf_(gxrow[u] + ghz + b1[u]);
                float r = sigmoidf_(gxrow[UU + u] + ghr + b1[UU + u]);
                float cc = tanhf(gxrow[2 * UU + u] + r * (ghc + b1[2 * UU + u]));
                enc_out[(size_t)(b * SS + t) * UU + u] = z * hold + (1.f - z) * cc;
            }
        }
        __syncthreads();
    }
}

// ---------------------------------------------------------------------------
// Decoder step (one block per batch b, 256 threads):
//   scores = h . enc_out ; softmax ; gx_ctx = sum_s w_s * P[b,s,:] ; GRU(h0=0)
// ---------------------------------------------------------------------------
__global__ __launch_bounds__(256) void dec_step_kernel(
    const float* __restrict__ h_prev, int hp_stride,
    const float* __restrict__ enc_out,
    const float* __restrict__ P,
    const float* __restrict__ gxd_t, int gxd_stride,
    const float* __restrict__ db1,
    float* __restrict__ h_out, int ho_stride)
{
    const int b = blockIdx.x;
    const int tid = threadIdx.x;
    const int warp = tid >> 5, lane = tid & 31;

    __shared__ float wsm[SS];
    __shared__ float gxc[G3];

    {
        const float* hb = h_prev + (size_t)b * hp_stride;
        const float* eb = enc_out + (size_t)b * SS * UU;
        float acc[5] = {0.f, 0.f, 0.f, 0.f, 0.f};
#pragma unroll 4
        for (int i = 0; i < 32; i++) {
            int uidx = lane + 32 * i;
            float hv = hb[uidx];
#pragma unroll
            for (int q = 0; q < 5; q++)
                acc[q] += hv * eb[(size_t)(warp * 5 + q) * UU + uidx];
        }
#pragma unroll
        for (int q = 0; q < 5; q++) {
            float v = acc[q];
            for (int o = 16; o; o >>= 1) v += __shfl_xor_sync(0xffffffffu, v, o);
            if (lane == 0) wsm[warp * 5 + q] = v;
        }
    }
    __syncthreads();

    if (tid == 0) {
        float mx = -1e30f;
        for (int s = 0; s < SS; s++) mx = fmaxf(mx, wsm[s]);
        float sm = 0.f;
        for (int s = 0; s < SS; s++) { float e = expf(wsm[s] - mx); wsm[s] = e; sm += e; }
        float inv = 1.f / sm;
        for (int s = 0; s < SS; s++) wsm[s] *= inv;
    }
    __syncthreads();

    {
        const float* Pb = P + (size_t)b * SS * G3;
        float a[12];
#pragma unroll
        for (int i = 0; i < 12; i++) a[i] = 0.f;
        for (int s = 0; s < SS; s++) {
            float w = wsm[s];
            const float* row = Pb + (size_t)s * G3;
#pragma unroll
            for (int i = 0; i < 12; i++)
                a[i] += w * row[tid + i * 256];
        }
#pragma unroll
        for (int i = 0; i < 12; i++) gxc[tid + i * 256] = a[i];
    }
    __syncthreads();

    {
        const float* gx = gxd_t + (size_t)b * gxd_stride;
        float* ho = h_out + (size_t)b * ho_stride;
#pragma unroll
        for (int i = 0; i < 4; i++) {
            int u = tid + i * 256;
            float z = sigmoidf_(gxc[u] + gx[u] + db1[u]);
            float r = sigmoidf_(gxc[UU + u] + gx[UU + u] + db1[UU + u]);
            float c = tanhf(gxc[2 * UU + u] + gx[2 * UU + u] + r * db1[2 * UU + u]);
            ho[u] = (1.f - z) * c;
        }
    }
}

// ---------------------------------------------------------------------------
extern "C" void kernel_launch(void* const* d_in, const int* in_sizes, int n_in,
                              void* d_out, int out_size)
{
    const int*   inp     = (const int*)d_in[0];
    const int*   targ    = (const int*)d_in[1];
    const float* enc_emb = (const float*)d_in[2];
    const float* enc_Wx  = (const float*)d_in[3];
    const float* enc_Wh  = (const float*)d_in[4];
    const float* enc_b   = (const float*)d_in[5];
    const float* dec_emb = (const float*)d_in[6];
    const float* dec_Wx  = (const float*)d_in[7];
    // d_in[8] = dec_Wh: provably unused (decoder GRU hidden input is zeros)
    const float* dec_b   = (const float*)d_in[9];
    const float* fc_W    = (const float*)d_in[10];
    const float* fc_b    = (const float*)d_in[11];
    float* out = (float*)d_out;

    float *gxe, *gxd, *enc_out, *P, *hdec;
    unsigned* bar;
    cudaGetSymbolAddress((void**)&gxe,     g_gxe);
    cudaGetSymbolAddress((void**)&gxd,     g_gxd);
    cudaGetSymbolAddress((void**)&enc_out, g_enc_out);
    cudaGetSymbolAddress((void**)&P,       g_P);
    cudaGetSymbolAddress((void**)&hdec,    g_hdec);
    cudaGetSymbolAddress((void**)&bar,     g_bar);

    cudaFuncSetAttribute(enc_persistent,
                         cudaFuncAttributeMaxDynamicSharedMemorySize, ENC_SMEM_BYTES);

    // 1) Encoder gx (fp32 — feeds the recurrence, keep full precision)
    gemm_f32<<<dim3(G3 / 128, (BB * SS + 127) / 128), 256>>>(
        nullptr, enc_emb, inp, SS, SS, EE,
        enc_Wx, G3, enc_b, gxe, BB * SS, G3, EE);

    // 2) Decoder xt-part gx (tf32 tensor path)
    gemm_tf32<<<dim3(G3 / 128, (BB * TD + 127) / 128), 256>>>(
        nullptr, dec_emb, targ, TD, SS, EE,
        dec_Wx + (size_t)UU * G3, G3, dec_b, gxd, BB * TD, G3, EE);

    // 3) Encoder recurrence: persistent kernel, k-split warps
    enc_persistent<<<ENC_BLOCKS, ENC_THREADS, ENC_SMEM_BYTES>>>(
        gxe, enc_Wh, enc_b + G3, enc_out, bar, bar + 1);

    // 4) P = enc_out @ dec_Wx[:U]   (tf32 tensor path)
    gemm_tf32<<<dim3(G3 / 128, (BB * SS + 127) / 128), 256>>>(
        enc_out, nullptr, nullptr, 1, 1, UU,
        dec_Wx, G3, nullptr, P, BB * SS, G3, UU);

    // 5) Decoder recurrence
    for (int t = 0; t < TD; t++) {
        const float* hp;
        int hps;
        if (t == 0) { hp = enc_out + (size_t)(SS - 1) * UU; hps = SS * UU; }
        else        { hp = hdec + (size_t)(t - 1) * UU;     hps = TD * UU; }
        dec_step_kernel<<<BB, 256>>>(
            hp, hps, enc_out, P,
            gxd + (size_t)t * G3, TD * G3,
            dec_b + G3,
            hdec + (size_t)t * UU, TD * UU);
    }

    // 6) Batched output projection (tf32 tensor path)
    gemm_tf32<<<dim3(VV / 128, (BB * TD + 127) / 128), 256>>>(
        hdec, nullptr, nullptr, 1, 1, UU,
        fc_W, VV, fc_b, out, BB * TD, VV, UU);
}

// round 9
// speedup vs baseline: 1.3282x; 1.0199x over previous
#include <cuda_runtime.h>
#include <math.h>
#include <stdint.h>
#include <string.h>

#define BB 64
#define SS 40
#define TD 39
#define EE 256
#define UU 1024
#define VV 8192
#define G3 3072

// Scratch (device globals; no allocation allowed)
static __device__ float g_gxe[BB * SS * G3];      // encoder x@Wx + b0
static __device__ float g_gxd[BB * TD * G3];      // decoder xt@Wx_bot + b0
static __device__ float g_enc_out[BB * SS * UU];  // encoder hidden sequence
static __device__ float g_P[BB * SS * G3];        // enc_out @ dec_Wx[:U]
static __device__ float g_hdec[BB * TD * UU];     // decoder hidden per step
static __device__ unsigned g_bar[2];              // [0]=count, [1]=release epoch

// ---------------------------------------------------------------------------
// packed fp32x2 FMA (2x FFMA pipe throughput on sm_103a)
// ---------------------------------------------------------------------------
__device__ __forceinline__ float2 fma2(float2 a, float2 b, float2 c) {
    unsigned long long ua, ub, uc;
    memcpy(&ua, &a, 8); memcpy(&ub, &b, 8); memcpy(&uc, &c, 8);
    asm("fma.rn.f32x2 %0, %1, %2, %0;" : "+l"(uc) : "l"(ua), "l"(ub));
    float2 r; memcpy(&r, &uc, 8);
    return r;
}

__device__ __forceinline__ float sigmoidf_(float x) {
    return 1.0f / (1.0f + expf(-x));
}

__device__ __forceinline__ uint32_t f2tf32(float x) {
    uint32_t r;
    asm("cvt.rna.tf32.f32 %0, %1;" : "=r"(r) : "f"(x));
    return r;
}

__device__ __forceinline__ void mma_tf32(float c[4], const uint32_t a[4],
                                         const uint32_t b[2]) {
    asm("mma.sync.aligned.m16n8k8.row.col.f32.tf32.tf32.f32 "
        "{%0,%1,%2,%3},{%4,%5,%6,%7},{%8,%9},{%0,%1,%2,%3};"
        : "+f"(c[0]), "+f"(c[1]), "+f"(c[2]), "+f"(c[3])
        : "r"(a[0]), "r"(a[1]), "r"(a[2]), "r"(a[3]), "r"(b[0]), "r"(b[1]));
}

// ---------------------------------------------------------------------------
// fp32 GEMM (scalar f32x2 path) — step 1 only (feeds the recurrence).
// ---------------------------------------------------------------------------
__global__ __launch_bounds__(256, 2) void gemm_f32(
    const float* __restrict__ A,
    const float* __restrict__ emb, const int* __restrict__ idx,
    int idxTT, int idxStride, int lda,
    const float* __restrict__ W, int ldw,
    const float* __restrict__ bias,
    float* __restrict__ C, int M, int N, int K)
{
    __shared__ __align__(16) float As[2][8][128];
    __shared__ __align__(16) float Ws[2][8][128];

    const int tid = threadIdx.x;
    const int bm = blockIdx.y * 128;
    const int bn = blockIdx.x * 128;

    const int arow_l = tid & 127;
    const int akh    = tid >> 7;
    int mload = bm + arow_l;
    if (mload >= M) mload = M - 1;
    const float* arow;
    if (emb) {
        int r = idx[(mload / idxTT) * idxStride + (mload % idxTT)];
        arow = emb + (size_t)r * lda;
    } else {
        arow = A + (size_t)mload * lda;
    }

    const int wk = tid >> 5;
    const int wn = (tid & 31) * 4;
    const float* wptr = W + (size_t)wk * ldw + bn + wn;

    const int tx = tid & 15, ty = tid >> 4;
    const int r0 = ty * 8, c0 = tx * 8;

    float2 acc[8][4];
#pragma unroll
    for (int r = 0; r < 8; r++)
#pragma unroll
        for (int c = 0; c < 4; c++) acc[r][c] = make_float2(0.f, 0.f);

    const int nIter = K >> 3;

    float4 av = *reinterpret_cast<const float4*>(arow + akh * 4);
    float4 wv = *reinterpret_cast<const float4*>(wptr);
    As[0][akh * 4 + 0][arow_l] = av.x;
    As[0][akh * 4 + 1][arow_l] = av.y;
    As[0][akh * 4 + 2][arow_l] = av.z;
    As[0][akh * 4 + 3][arow_l] = av.w;
    *reinterpret_cast<float4*>(&Ws[0][wk][wn]) = wv;
    __syncthreads();

    for (int it = 0; it < nIter; it++) {
        const int cur = it & 1;
        if (it + 1 < nIter) {
            av = *reinterpret_cast<const float4*>(arow + (it + 1) * 8 + akh * 4);
            wv = *reinterpret_cast<const float4*>(wptr + (size_t)(it + 1) * 8 * ldw);
        }
#pragma unroll
        for (int k = 0; k < 8; k++) {
            float4 a0 = *reinterpret_cast<const float4*>(&As[cur][k][r0]);
            float4 a1 = *reinterpret_cast<const float4*>(&As[cur][k][r0 + 4]);
            float4 w0 = *reinterpret_cast<const float4*>(&Ws[cur][k][c0]);
            float4 w1 = *reinterpret_cast<const float4*>(&Ws[cur][k][c0 + 4]);
            float2 w[4];
            w[0] = make_float2(w0.x, w0.y);
            w[1] = make_float2(w0.z, w0.w);
            w[2] = make_float2(w1.x, w1.y);
            w[3] = make_float2(w1.z, w1.w);
            float ar[8] = {a0.x, a0.y, a0.z, a0.w, a1.x, a1.y, a1.z, a1.w};
#pragma unroll
            for (int r = 0; r < 8; r++) {
                float2 ad = make_float2(ar[r], ar[r]);
#pragma unroll
                for (int c = 0; c < 4; c++)
                    acc[r][c] = fma2(ad, w[c], acc[r][c]);
            }
        }
        if (it + 1 < nIter) {
            const int nxt = cur ^ 1;
            As[nxt][akh * 4 + 0][arow_l] = av.x;
            As[nxt][akh * 4 + 1][arow_l] = av.y;
            As[nxt][akh * 4 + 2][arow_l] = av.z;
            As[nxt][akh * 4 + 3][arow_l] = av.w;
            *reinterpret_cast<float4*>(&Ws[nxt][wk][wn]) = wv;
            __syncthreads();
        }
    }

    float bv[8];
#pragma unroll
    for (int j = 0; j < 8; j++) bv[j] = bias ? bias[bn + c0 + j] : 0.f;
#pragma unroll
    for (int r = 0; r < 8; r++) {
        int mrow = bm + r0 + r;
        if (mrow < M) {
            float4 o0, o1;
            o0.x = acc[r][0].x + bv[0];
            o0.y = acc[r][0].y + bv[1];
            o0.z = acc[r][1].x + bv[2];
            o0.w = acc[r][1].y + bv[3];
            o1.x = acc[r][2].x + bv[4];
            o1.y = acc[r][2].y + bv[5];
            o1.z = acc[r][3].x + bv[6];
            o1.w = acc[r][3].y + bv[7];
            *reinterpret_cast<float4*>(C + (size_t)mrow * N + bn + c0)     = o0;
            *reinterpret_cast<float4*>(C + (size_t)mrow * N + bn + c0 + 4) = o1;
        }
    }
}

// ---------------------------------------------------------------------------
// tf32 tensor-core GEMM (mma.sync m16n8k8) — steps 2, 4, 6.
// ---------------------------------------------------------------------------
#define TFS 136

__global__ __launch_bounds__(256) void gemm_tf32(
    const float* __restrict__ A,
    const float* __restrict__ emb, const int* __restrict__ idx,
    int idxTT, int idxStride, int lda,
    const float* __restrict__ W, int ldw,
    const float* __restrict__ bias,
    float* __restrict__ C, int M, int N, int K)
{
    __shared__ __align__(16) uint32_t Ast[2][16][TFS];
    __shared__ __align__(16) uint32_t Bst[2][16][TFS];

    const int tid  = threadIdx.x;
    const int lane = tid & 31;
    const int wid  = tid >> 5;
    const int wm   = wid & 3;
    const int wn   = wid >> 2;
    const int g    = lane >> 2;
    const int qt   = lane & 3;

    const int bm = blockIdx.y * 128;
    const int bn = blockIdx.x * 128;

    const int arow_l = tid & 127;
    const int akh    = tid >> 7;
    int mload = bm + arow_l;
    if (mload >= M) mload = M - 1;
    const float* arow;
    if (emb) {
        int r = idx[(mload / idxTT) * idxStride + (mload % idxTT)];
        arow = emb + (size_t)r * lda;
    } else {
        arow = A + (size_t)mload * lda;
    }

    const int wk  = tid >> 5;
    const int wn4 = (tid & 31) * 4;
    const float* wptr = W + (size_t)wk * ldw + bn + wn4;

    float acc[2][8][4];
#pragma unroll
    for (int mf = 0; mf < 2; mf++)
#pragma unroll
        for (int nf = 0; nf < 8; nf++)
#pragma unroll
            for (int q = 0; q < 4; q++) acc[mf][nf][q] = 0.f;

    const int nIter = K >> 4;

    float4 av0 = *reinterpret_cast<const float4*>(arow + akh * 8);
    float4 av1 = *reinterpret_cast<const float4*>(arow + akh * 8 + 4);
    float4 wv0 = *reinterpret_cast<const float4*>(wptr);
    float4 wv1 = *reinterpret_cast<const float4*>(wptr + (size_t)8 * ldw);
    {
        const float a0[8] = {av0.x, av0.y, av0.z, av0.w, av1.x, av1.y, av1.z, av1.w};
#pragma unroll
        for (int j = 0; j < 8; j++) Ast[0][akh * 8 + j][arow_l] = f2tf32(a0[j]);
        uint4 p0 = make_uint4(f2tf32(wv0.x), f2tf32(wv0.y), f2tf32(wv0.z), f2tf32(wv0.w));
        uint4 p1 = make_uint4(f2tf32(wv1.x), f2tf32(wv1.y), f2tf32(wv1.z), f2tf32(wv1.w));
        *reinterpret_cast<uint4*>(&Bst[0][wk][wn4])     = p0;
        *reinterpret_cast<uint4*>(&Bst[0][wk + 8][wn4]) = p1;
    }
    __syncthreads();

    for (int it = 0; it < nIter; it++) {
        const int cur = it & 1;
        if (it + 1 < nIter) {
            av0 = *reinterpret_cast<const float4*>(arow + (it + 1) * 16 + akh * 8);
            av1 = *reinterpret_cast<const float4*>(arow + (it + 1) * 16 + akh * 8 + 4);
            wv0 = *reinterpret_cast<const float4*>(wptr + (size_t)(it + 1) * 16 * ldw);
            wv1 = *reinterpret_cast<const float4*>(wptr + (size_t)((it + 1) * 16 + 8) * ldw);
        }
#pragma unroll
        for (int k8 = 0; k8 < 2; k8++) {
            uint32_t afrag[2][4];
#pragma unroll
            for (int mf = 0; mf < 2; mf++) {
                int R = wm * 32 + mf * 16;
                afrag[mf][0] = Ast[cur][k8 * 8 + qt][R + g];
                afrag[mf][1] = Ast[cur][k8 * 8 + qt][R + g + 8];
                afrag[mf][2] = Ast[cur][k8 * 8 + qt + 4][R + g];
                afrag[mf][3] = Ast[cur][k8 * 8 + qt + 4][R + g + 8];
            }
#pragma unroll
            for (int nf = 0; nf < 8; nf++) {
                uint32_t bfrag[2];
                int cidx = wn * 64 + nf * 8 + g;
                bfrag[0] = Bst[cur][k8 * 8 + qt][cidx];
                bfrag[1] = Bst[cur][k8 * 8 + qt + 4][cidx];
                mma_tf32(acc[0][nf], afrag[0], bfrag);
                mma_tf32(acc[1][nf], afrag[1], bfrag);
            }
        }
        if (it + 1 < nIter) {
            const int nxt = cur ^ 1;
            const float a0[8] = {av0.x, av0.y, av0.z, av0.w, av1.x, av1.y, av1.z, av1.w};
#pragma unroll
            for (int j = 0; j < 8; j++) Ast[nxt][akh * 8 + j][arow_l] = f2tf32(a0[j]);
            uint4 p0 = make_uint4(f2tf32(wv0.x), f2tf32(wv0.y), f2tf32(wv0.z), f2tf32(wv0.w));
            uint4 p1 = make_uint4(f2tf32(wv1.x), f2tf32(wv1.y), f2tf32(wv1.z), f2tf32(wv1.w));
            *reinterpret_cast<uint4*>(&Bst[nxt][wk][wn4])     = p0;
            *reinterpret_cast<uint4*>(&Bst[nxt][wk + 8][wn4]) = p1;
            __syncthreads();
        }
    }

#pragma unroll
    for (int nf = 0; nf < 8; nf++) {
        int colb = bn + wn * 64 + nf * 8 + qt * 2;
        float b0 = bias ? bias[colb]     : 0.f;
        float b1 = bias ? bias[colb + 1] : 0.f;
#pragma unroll
        for (int mf = 0; mf < 2; mf++) {
            int row0 = bm + wm * 32 + mf * 16 + g;
            if (row0 < M) {
                float2 v = make_float2(acc[mf][nf][0] + b0, acc[mf][nf][1] + b1);
                *reinterpret_cast<float2*>(C + (size_t)row0 * N + colb) = v;
            }
            int row1 = row0 + 8;
            if (row1 < M) {
                float2 v = make_float2(acc[mf][nf][2] + b0, acc[mf][nf][3] + b1);
                *reinterpret_cast<float2*>(C + (size_t)row1 * N + colb) = v;
            }
        }
    }
}

// ---------------------------------------------------------------------------
// Persistent encoder recurrence v3. ONE launch for all 40 steps.
// 128 blocks x 512 threads; block bi owns u in [bi*8, bi*8+8) (24 gate cols).
// 16 warps = 8 k-splits (128 k each) x 2 row-half warps (32 rows each).
// Thread microtile: 4 rows x 3 col-pairs -> 12 fma2 per k vs 5 LDS.64.
// h staged per-ksplit in double-buffered 8k x 64row smem chunks, synced by
// named pair barriers. Partial gh reduced over 8 k-splits in smem.
// Wh slice (96KB) cached in shared once. Grid barrier between steps.
// ---------------------------------------------------------------------------
#define ENC_BLOCKS 128
#define ENC_THREADS 512
#define WSH_FLOATS (1024 * 24)
#define HCH_FLOATS 528            /* 8 k x 66 */
#define HST_FLOATS (8 * 2 * HCH_FLOATS)
#define GHP_STRIDE 26
#define GHP_FLOATS (8 * 64 * GHP_STRIDE)
#define ENC_SMEM_FLOATS (WSH_FLOATS + HST_FLOATS + GHP_FLOATS)
#define ENC_SMEM_BYTES (ENC_SMEM_FLOATS * 4)

#define PAIRBAR(s) asm volatile("bar.sync %0, 64;" :: "r"(1 + (s)) : "memory")

__global__ __launch_bounds__(ENC_THREADS, 1) void enc_persistent(
    const float* __restrict__ gxe,   // [B*S][3U]  (includes b0)
    const float* __restrict__ Wh,    // [U][3U]
    const float* __restrict__ b1,    // [3U]
    float* __restrict__ enc_out,     // [B*S][U]
    unsigned* bar_cnt, unsigned* bar_rel)
{
    extern __shared__ float sm[];
    float* Wsh = sm;                           // [1024][24]
    float* hst = sm + WSH_FLOATS;              // [8 ksplit][2 buf][8 k][66]
    float* ghp = sm + WSH_FLOATS + HST_FLOATS; // [8 ksplit][64][26]

    const int tid  = threadIdx.x;
    const int wid  = tid >> 5;
    const int lane = tid & 31;
    const int s    = wid >> 1;        // ksplit 0..7
    const int wp   = wid & 1;         // row half 0..1
    const int rg   = lane >> 2;       // 0..7 -> rows wp*32 + rg*4 .. +3
    const int cg   = lane & 3;        // col-pair group: pairs cg*3..cg*3+2
    const int bi   = blockIdx.x;
    const int u0   = bi * 8;
    const int ks   = s * 128;
    const int row_l = wp * 32 + lane; // staging row 0..63
    const int rbase = wp * 32 + rg * 4;

    float* hstS = hst + s * 2 * HCH_FLOATS;
    float* ghpS = ghp + s * 64 * GHP_STRIDE;

    // Preload Wh slice: Wsh[k][gate*8+du] = Wh[k][gate*1024+u0+du]
    for (int i = tid; i < WSH_FLOATS; i += ENC_THREADS) {
        int k = i / 24, c = i % 24;
        Wsh[i] = Wh[(size_t)k * G3 + (c >> 3) * UU + u0 + (c & 7)];
    }

    __shared__ unsigned relbase_s;
    if (tid == 0) relbase_s = *(volatile unsigned*)bar_rel;
    __syncthreads();
    const unsigned relbase = relbase_s;

    // per-thread epilogue constants (t-invariant)
    const int eb  = tid >> 3;         // batch 0..63
    const int edu = tid & 7;
    const int eu  = u0 + edu;
    const float b1z = b1[eu], b1r = b1[UU + eu], b1c = b1[2 * UU + eu];

    for (int t = 0; t < SS; t++) {
        if (t > 0) {
            // ---- grid barrier: all blocks wrote h_{t-1} ----
            __threadfence();
            __syncthreads();
            if (tid == 0) {
                unsigned old = atomicAdd(bar_cnt, 1u);
                if (old == ENC_BLOCKS - 1) {
                    atomicExch(bar_cnt, 0u);
                    __threadfence();
                    atomicAdd(bar_rel, 1u);
                }
                while (*(volatile unsigned*)bar_rel - relbase < (unsigned)t) {}
            }
            __syncthreads();
            __threadfence();

            float2 acc[4][3];
#pragma unroll
            for (int r = 0; r < 4; r++)
#pragma unroll
                for (int j = 0; j < 3; j++) acc[r][j] = make_float2(0.f, 0.f);

            const float* hrow = enc_out + (size_t)(t - 1) * UU +
                                (size_t)row_l * (SS * UU) + ks;
            float* h0 = hstS;
            float* h1 = hstS + HCH_FLOATS;

            // prologue: stage chunk 0
            float4 pa = *reinterpret_cast<const float4*>(hrow);
            float4 pb = *reinterpret_cast<const float4*>(hrow + 4);
            {
                float a[8] = {pa.x, pa.y, pa.z, pa.w, pb.x, pb.y, pb.z, pb.w};
#pragma unroll
                for (int j = 0; j < 8; j++) h0[j * 66 + row_l] = a[j];
            }
            PAIRBAR(s);

            for (int c = 0; c < 16; c++) {
                if (c + 1 < 16) {
                    pa = *reinterpret_cast<const float4*>(hrow + (c + 1) * 8);
                    pb = *reinterpret_cast<const float4*>(hrow + (c + 1) * 8 + 4);
                }
                const float* hb = (c & 1) ? h1 : h0;
                const float* wb = Wsh + (size_t)(ks + c * 8) * 24 + cg * 6;
#pragma unroll
                for (int kk = 0; kk < 8; kk++) {
                    const float* hk = hb + kk * 66 + rbase;
                    float2 hp0 = *reinterpret_cast<const float2*>(hk);
                    float2 hp1 = *reinterpret_cast<const float2*>(hk + 2);
                    const float* wr = wb + kk * 24;
                    float2 w0 = *reinterpret_cast<const float2*>(wr);
                    float2 w1 = *reinterpret_cast<const float2*>(wr + 2);
                    float2 w2 = *reinterpret_cast<const float2*>(wr + 4);
                    float2 d0 = make_float2(hp0.x, hp0.x);
                    float2 d1 = make_float2(hp0.y, hp0.y);
                    float2 d2 = make_float2(hp1.x, hp1.x);
                    float2 d3 = make_float2(hp1.y, hp1.y);
                    acc[0][0] = fma2(d0, w0, acc[0][0]);
                    acc[1][0] = fma2(d1, w0, acc[1][0]);
                    acc[2][0] = fma2(d2, w0, acc[2][0]);
                    acc[3][0] = fma2(d3, w0, acc[3][0]);
                    acc[0][1] = fma2(d0, w1, acc[0][1]);
                    acc[1][1] = fma2(d1, w1, acc[1][1]);
                    acc[2][1] = fma2(d2, w1, acc[2][1]);
                    acc[3][1] = fma2(d3, w1, acc[3][1]);
                    acc[0][2] = fma2(d0, w2, acc[0][2]);
                    acc[1][2] = fma2(d1, w2, acc[1][2]);
                    acc[2][2] = fma2(d2, w2, acc[2][2]);
                    acc[3][2] = fma2(d3, w2, acc[3][2]);
                }
                if (c + 1 < 16) {
                    float* hn = (c & 1) ? h0 : h1;
                    float a[8] = {pa.x, pa.y, pa.z, pa.w, pb.x, pb.y, pb.z, pb.w};
#pragma unroll
                    for (int j = 0; j < 8; j++) hn[j * 66 + row_l] = a[j];
                    PAIRBAR(s);
                }
            }

            // write partial gh for this ksplit
#pragma unroll
            for (int r = 0; r < 4; r++)
#pragma unroll
                for (int j = 0; j < 3; j++)
                    *reinterpret_cast<float2*>(
                        ghpS + (size_t)(rbase + r) * GHP_STRIDE + (cg * 3 + j) * 2) =
                        acc[r][j];
        }
        __syncthreads();

        // Epilogue: one (b,u) output per thread; reduce 8 ksplit partials
        {
            float ghz = 0.f, ghr = 0.f, ghc = 0.f, hold = 0.f;
            if (t > 0) {
#pragma unroll
                for (int s2 = 0; s2 < 8; s2++) {
                    const float* g = ghp + s2 * (64 * GHP_STRIDE) + eb * GHP_STRIDE;
                    ghz += g[edu];
                    ghr += g[8 + edu];
                    ghc += g[16 + edu];
                }
                hold = enc_out[(size_t)(eb * SS + t - 1) * UU + eu];
            }
            const float* gxrow = gxe + (size_t)(eb * SS + t) * G3;
            float z = sigmoidf_(gxrow[eu] + ghz + b1z);
            float r = sigmoidf_(gxrow[UU + eu] + ghr + b1r);
            float cc = tanhf(gxrow[2 * UU + eu] + r * (ghc + b1c));
            enc_out[(size_t)(eb * SS + t) * UU + eu] = z * hold + (1.f - z) * cc;
        }
    }
}

// ---------------------------------------------------------------------------
// Decoder step (one block per batch b, 256 threads)
// ---------------------------------------------------------------------------
__global__ __launch_bounds__(256) void dec_step_kernel(
    const float* __restrict__ h_prev, int hp_stride,
    const float* __restrict__ enc_out,
    const float* __restrict__ P,
    const float* __restrict__ gxd_t, int gxd_stride,
    const float* __restrict__ db1,
    float* __restrict__ h_out, int ho_stride)
{
    const int b = blockIdx.x;
    const int tid = threadIdx.x;
    const int warp = tid >> 5, lane = tid & 31;

    __shared__ float wsm[SS];
    __shared__ float gxc[G3];

    {
        const float* hb = h_prev + (size_t)b * hp_stride;
        const float* eb = enc_out + (size_t)b * SS * UU;
        float acc[5] = {0.f, 0.f, 0.f, 0.f, 0.f};
#pragma unroll 4
        for (int i = 0; i < 32; i++) {
            int uidx = lane + 32 * i;
            float hv = hb[uidx];
#pragma unroll
            for (int q = 0; q < 5; q++)
                acc[q] += hv * eb[(size_t)(warp * 5 + q) * UU + uidx];
        }
#pragma unroll
        for (int q = 0; q < 5; q++) {
            float v = acc[q];
            for (int o = 16; o; o >>= 1) v += __shfl_xor_sync(0xffffffffu, v, o);
            if (lane == 0) wsm[warp * 5 + q] = v;
        }
    }
    __syncthreads();

    if (tid == 0) {
        float mx = -1e30f;
        for (int s = 0; s < SS; s++) mx = fmaxf(mx, wsm[s]);
        float sm = 0.f;
        for (int s = 0; s < SS; s++) { float e = expf(wsm[s] - mx); wsm[s] = e; sm += e; }
        float inv = 1.f / sm;
        for (int s = 0; s < SS; s++) wsm[s] *= inv;
    }
    __syncthreads();

    {
        const float* Pb = P + (size_t)b * SS * G3;
        float a[12];
#pragma unroll
        for (int i = 0; i < 12; i++) a[i] = 0.f;
        for (int s = 0; s < SS; s++) {
            float w = wsm[s];
            const float* row = Pb + (size_t)s * G3;
#pragma unroll
            for (int i = 0; i < 12; i++)
                a[i] += w * row[tid + i * 256];
        }
#pragma unroll
        for (int i = 0; i < 12; i++) gxc[tid + i * 256] = a[i];
    }
    __syncthreads();

    {
        const float* gx = gxd_t + (size_t)b * gxd_stride;
        float* ho = h_out + (size_t)b * ho_stride;
#pragma unroll
        for (int i = 0; i < 4; i++) {
            int u = tid + i * 256;
            float z = sigmoidf_(gxc[u] + gx[u] + db1[u]);
            float r = sigmoidf_(gxc[UU + u] + gx[UU + u] + db1[UU + u]);
            float c = tanhf(gxc[2 * UU + u] + gx[2 * UU + u] + r * db1[2 * UU + u]);
            ho[u] = (1.f - z) * c;
        }
    }
}

// ---------------------------------------------------------------------------
extern "C" void kernel_launch(void* const* d_in, const int* in_sizes, int n_in,
                              void* d_out, int out_size)
{
    const int*   inp     = (const int*)d_in[0];
    const int*   targ    = (const int*)d_in[1];
    const float* enc_emb = (const float*)d_in[2];
    const float* enc_Wx  = (const float*)d_in[3];
    const float* enc_Wh  = (const float*)d_in[4];
    const float* enc_b   = (const float*)d_in[5];
    const float* dec_emb = (const float*)d_in[6];
    const float* dec_Wx  = (const float*)d_in[7];
    // d_in[8] = dec_Wh: provably unused (decoder GRU hidden input is zeros)
    const float* dec_b   = (const float*)d_in[9];
    const float* fc_W    = (const float*)d_in[10];
    const float* fc_b    = (const float*)d_in[11];
    float* out = (float*)d_out;

    float *gxe, *gxd, *enc_out, *P, *hdec;
    unsigned* bar;
    cudaGetSymbolAddress((void**)&gxe,     g_gxe);
    cudaGetSymbolAddress((void**)&gxd,     g_gxd);
    cudaGetSymbolAddress((void**)&enc_out, g_enc_out);
    cudaGetSymbolAddress((void**)&P,       g_P);
    cudaGetSymbolAddress((void**)&hdec,    g_hdec);
    cudaGetSymbolAddress((void**)&bar,     g_bar);

    cudaFuncSetAttribute(enc_persistent,
                         cudaFuncAttributeMaxDynamicSharedMemorySize, ENC_SMEM_BYTES);

    // 1) Encoder gx (fp32 — feeds the recurrence, keep full precision)
    gemm_f32<<<dim3(G3 / 128, (BB * SS + 127) / 128), 256>>>(
        nullptr, enc_emb, inp, SS, SS, EE,
        enc_Wx, G3, enc_b, gxe, BB * SS, G3, EE);

    // 2) Decoder xt-part gx (tf32 tensor path)
    gemm_tf32<<<dim3(G3 / 128, (BB * TD + 127) / 128), 256>>>(
        nullptr, dec_emb, targ, TD, SS, EE,
        dec_Wx + (size_t)UU * G3, G3, dec_b, gxd, BB * TD, G3, EE);

    // 3) Encoder recurrence: persistent kernel v3
    enc_persistent<<<ENC_BLOCKS, ENC_THREADS, ENC_SMEM_BYTES>>>(
        gxe, enc_Wh, enc_b + G3, enc_out, bar, bar + 1);

    // 4) P = enc_out @ dec_Wx[:U]   (tf32 tensor path)
    gemm_tf32<<<dim3(G3 / 128, (BB * SS + 127) / 128), 256>>>(
        enc_out, nullptr, nullptr, 1, 1, UU,
        dec_Wx, G3, nullptr, P, BB * SS, G3, UU);

    // 5) Decoder recurrence
    for (int t = 0; t < TD; t++) {
        const float* hp;
        int hps;
        if (t == 0) { hp = enc_out + (size_t)(SS - 1) * UU; hps = SS * UU; }
        else        { hp = hdec + (size_t)(t - 1) * UU;     hps = TD * UU; }
        dec_step_kernel<<<BB, 256>>>(
            hp, hps, enc_out, P,
            gxd + (size_t)t * G3, TD * G3,
            dec_b + G3,
            hdec + (size_t)t * UU, TD * UU);
    }

    // 6) Batched output projection (tf32 tensor path)
    gemm_tf32<<<dim3(VV / 128, (BB * TD + 127) / 128), 256>>>(
        hdec, nullptr, nullptr, 1, 1, UU,
        fc_W, VV, fc_b, out, BB * TD, VV, UU);
}

// round 10
// speedup vs baseline: 1.6993x; 1.2794x over previous
#include <cuda_runtime.h>
#include <math.h>
#include <stdint.h>
#include <string.h>

#define BB 64
#define SS 40
#define TD 39
#define EE 256
#define UU 1024
#define VV 8192
#define G3 3072

// Scratch (device globals; no allocation allowed)
static __device__ float g_gxe[BB * SS * G3];      // encoder x@Wx + b0
static __device__ float g_gxd[BB * TD * G3];      // decoder xt@Wx_bot + b0
static __device__ float g_enc_out[BB * SS * UU];  // encoder hidden sequence
static __device__ float g_P[BB * SS * G3];        // enc_out @ dec_Wx[:U]
static __device__ float g_hdec[BB * TD * UU];     // decoder hidden per step
static __device__ unsigned g_bar[2];              // [0]=count, [1]=release epoch

// ---------------------------------------------------------------------------
__device__ __forceinline__ float2 fma2(float2 a, float2 b, float2 c) {
    unsigned long long ua, ub, uc;
    memcpy(&ua, &a, 8); memcpy(&ub, &b, 8); memcpy(&uc, &c, 8);
    asm("fma.rn.f32x2 %0, %1, %2, %0;" : "+l"(uc) : "l"(ua), "l"(ub));
    float2 r; memcpy(&r, &uc, 8);
    return r;
}

__device__ __forceinline__ float sigmoidf_(float x) {
    return 1.0f / (1.0f + expf(-x));
}

__device__ __forceinline__ uint32_t f2tf32(float x) {
    uint32_t r;
    asm("cvt.rna.tf32.f32 %0, %1;" : "=r"(r) : "f"(x));
    return r;
}

__device__ __forceinline__ void mma_tf32(float c[4], const uint32_t a[4],
                                         const uint32_t b[2]) {
    asm("mma.sync.aligned.m16n8k8.row.col.f32.tf32.tf32.f32 "
        "{%0,%1,%2,%3},{%4,%5,%6,%7},{%8,%9},{%0,%1,%2,%3};"
        : "+f"(c[0]), "+f"(c[1]), "+f"(c[2]), "+f"(c[3])
        : "r"(a[0]), "r"(a[1]), "r"(a[2]), "r"(a[3]), "r"(b[0]), "r"(b[1]));
}

// ---------------------------------------------------------------------------
// fp32 GEMM (scalar f32x2 path) — step 1 only (feeds the recurrence).
// ---------------------------------------------------------------------------
__global__ __launch_bounds__(256, 2) void gemm_f32(
    const float* __restrict__ A,
    const float* __restrict__ emb, const int* __restrict__ idx,
    int idxTT, int idxStride, int lda,
    const float* __restrict__ W, int ldw,
    const float* __restrict__ bias,
    float* __restrict__ C, int M, int N, int K)
{
    __shared__ __align__(16) float As[2][8][128];
    __shared__ __align__(16) float Ws[2][8][128];

    const int tid = threadIdx.x;
    const int bm = blockIdx.y * 128;
    const int bn = blockIdx.x * 128;

    const int arow_l = tid & 127;
    const int akh    = tid >> 7;
    int mload = bm + arow_l;
    if (mload >= M) mload = M - 1;
    const float* arow;
    if (emb) {
        int r = idx[(mload / idxTT) * idxStride + (mload % idxTT)];
        arow = emb + (size_t)r * lda;
    } else {
        arow = A + (size_t)mload * lda;
    }

    const int wk = tid >> 5;
    const int wn = (tid & 31) * 4;
    const float* wptr = W + (size_t)wk * ldw + bn + wn;

    const int tx = tid & 15, ty = tid >> 4;
    const int r0 = ty * 8, c0 = tx * 8;

    float2 acc[8][4];
#pragma unroll
    for (int r = 0; r < 8; r++)
#pragma unroll
        for (int c = 0; c < 4; c++) acc[r][c] = make_float2(0.f, 0.f);

    const int nIter = K >> 3;

    float4 av = *reinterpret_cast<const float4*>(arow + akh * 4);
    float4 wv = *reinterpret_cast<const float4*>(wptr);
    As[0][akh * 4 + 0][arow_l] = av.x;
    As[0][akh * 4 + 1][arow_l] = av.y;
    As[0][akh * 4 + 2][arow_l] = av.z;
    As[0][akh * 4 + 3][arow_l] = av.w;
    *reinterpret_cast<float4*>(&Ws[0][wk][wn]) = wv;
    __syncthreads();

    for (int it = 0; it < nIter; it++) {
        const int cur = it & 1;
        if (it + 1 < nIter) {
            av = *reinterpret_cast<const float4*>(arow + (it + 1) * 8 + akh * 4);
            wv = *reinterpret_cast<const float4*>(wptr + (size_t)(it + 1) * 8 * ldw);
        }
#pragma unroll
        for (int k = 0; k < 8; k++) {
            float4 a0 = *reinterpret_cast<const float4*>(&As[cur][k][r0]);
            float4 a1 = *reinterpret_cast<const float4*>(&As[cur][k][r0 + 4]);
            float4 w0 = *reinterpret_cast<const float4*>(&Ws[cur][k][c0]);
            float4 w1 = *reinterpret_cast<const float4*>(&Ws[cur][k][c0 + 4]);
            float2 w[4];
            w[0] = make_float2(w0.x, w0.y);
            w[1] = make_float2(w0.z, w0.w);
            w[2] = make_float2(w1.x, w1.y);
            w[3] = make_float2(w1.z, w1.w);
            float ar[8] = {a0.x, a0.y, a0.z, a0.w, a1.x, a1.y, a1.z, a1.w};
#pragma unroll
            for (int r = 0; r < 8; r++) {
                float2 ad = make_float2(ar[r], ar[r]);
#pragma unroll
                for (int c = 0; c < 4; c++)
                    acc[r][c] = fma2(ad, w[c], acc[r][c]);
            }
        }
        if (it + 1 < nIter) {
            const int nxt = cur ^ 1;
            As[nxt][akh * 4 + 0][arow_l] = av.x;
            As[nxt][akh * 4 + 1][arow_l] = av.y;
            As[nxt][akh * 4 + 2][arow_l] = av.z;
            As[nxt][akh * 4 + 3][arow_l] = av.w;
            *reinterpret_cast<float4*>(&Ws[nxt][wk][wn]) = wv;
            __syncthreads();
        }
    }

    float bv[8];
#pragma unroll
    for (int j = 0; j < 8; j++) bv[j] = bias ? bias[bn + c0 + j] : 0.f;
#pragma unroll
    for (int r = 0; r < 8; r++) {
        int mrow = bm + r0 + r;
        if (mrow < M) {
            float4 o0, o1;
            o0.x = acc[r][0].x + bv[0];
            o0.y = acc[r][0].y + bv[1];
            o0.z = acc[r][1].x + bv[2];
            o0.w = acc[r][1].y + bv[3];
            o1.x = acc[r][2].x + bv[4];
            o1.y = acc[r][2].y + bv[5];
            o1.z = acc[r][3].x + bv[6];
            o1.w = acc[r][3].y + bv[7];
            *reinterpret_cast<float4*>(C + (size_t)mrow * N + bn + c0)     = o0;
            *reinterpret_cast<float4*>(C + (size_t)mrow * N + bn + c0 + 4) = o1;
        }
    }
}

// ---------------------------------------------------------------------------
// tf32 tensor-core GEMM (mma.sync m16n8k8) — steps 2, 4, 6.
// ---------------------------------------------------------------------------
#define TFS 136

__global__ __launch_bounds__(256) void gemm_tf32(
    const float* __restrict__ A,
    const float* __restrict__ emb, const int* __restrict__ idx,
    int idxTT, int idxStride, int lda,
    const float* __restrict__ W, int ldw,
    const float* __restrict__ bias,
    float* __restrict__ C, int M, int N, int K)
{
    __shared__ __align__(16) uint32_t Ast[2][16][TFS];
    __shared__ __align__(16) uint32_t Bst[2][16][TFS];

    const int tid  = threadIdx.x;
    const int lane = tid & 31;
    const int wid  = tid >> 5;
    const int wm   = wid & 3;
    const int wn   = wid >> 2;
    const int g    = lane >> 2;
    const int qt   = lane & 3;

    const int bm = blockIdx.y * 128;
    const int bn = blockIdx.x * 128;

    const int arow_l = tid & 127;
    const int akh    = tid >> 7;
    int mload = bm + arow_l;
    if (mload >= M) mload = M - 1;
    const float* arow;
    if (emb) {
        int r = idx[(mload / idxTT) * idxStride + (mload % idxTT)];
        arow = emb + (size_t)r * lda;
    } else {
        arow = A + (size_t)mload * lda;
    }

    const int wk  = tid >> 5;
    const int wn4 = (tid & 31) * 4;
    const float* wptr = W + (size_t)wk * ldw + bn + wn4;

    float acc[2][8][4];
#pragma unroll
    for (int mf = 0; mf < 2; mf++)
#pragma unroll
        for (int nf = 0; nf < 8; nf++)
#pragma unroll
            for (int q = 0; q < 4; q++) acc[mf][nf][q] = 0.f;

    const int nIter = K >> 4;

    float4 av0 = *reinterpret_cast<const float4*>(arow + akh * 8);
    float4 av1 = *reinterpret_cast<const float4*>(arow + akh * 8 + 4);
    float4 wv0 = *reinterpret_cast<const float4*>(wptr);
    float4 wv1 = *reinterpret_cast<const float4*>(wptr + (size_t)8 * ldw);
    {
        const float a0[8] = {av0.x, av0.y, av0.z, av0.w, av1.x, av1.y, av1.z, av1.w};
#pragma unroll
        for (int j = 0; j < 8; j++) Ast[0][akh * 8 + j][arow_l] = f2tf32(a0[j]);
        uint4 p0 = make_uint4(f2tf32(wv0.x), f2tf32(wv0.y), f2tf32(wv0.z), f2tf32(wv0.w));
        uint4 p1 = make_uint4(f2tf32(wv1.x), f2tf32(wv1.y), f2tf32(wv1.z), f2tf32(wv1.w));
        *reinterpret_cast<uint4*>(&Bst[0][wk][wn4])     = p0;
        *reinterpret_cast<uint4*>(&Bst[0][wk + 8][wn4]) = p1;
    }
    __syncthreads();

    for (int it = 0; it < nIter; it++) {
        const int cur = it & 1;
        if (it + 1 < nIter) {
            av0 = *reinterpret_cast<const float4*>(arow + (it + 1) * 16 + akh * 8);
            av1 = *reinterpret_cast<const float4*>(arow + (it + 1) * 16 + akh * 8 + 4);
            wv0 = *reinterpret_cast<const float4*>(wptr + (size_t)(it + 1) * 16 * ldw);
            wv1 = *reinterpret_cast<const float4*>(wptr + (size_t)((it + 1) * 16 + 8) * ldw);
        }
#pragma unroll
        for (int k8 = 0; k8 < 2; k8++) {
            uint32_t afrag[2][4];
#pragma unroll
            for (int mf = 0; mf < 2; mf++) {
                int R = wm * 32 + mf * 16;
                afrag[mf][0] = Ast[cur][k8 * 8 + qt][R + g];
                afrag[mf][1] = Ast[cur][k8 * 8 + qt][R + g + 8];
                afrag[mf][2] = Ast[cur][k8 * 8 + qt + 4][R + g];
                afrag[mf][3] = Ast[cur][k8 * 8 + qt + 4][R + g + 8];
            }
#pragma unroll
            for (int nf = 0; nf < 8; nf++) {
                uint32_t bfrag[2];
                int cidx = wn * 64 + nf * 8 + g;
                bfrag[0] = Bst[cur][k8 * 8 + qt][cidx];
                bfrag[1] = Bst[cur][k8 * 8 + qt + 4][cidx];
                mma_tf32(acc[0][nf], afrag[0], bfrag);
                mma_tf32(acc[1][nf], afrag[1], bfrag);
            }
        }
        if (it + 1 < nIter) {
            const int nxt = cur ^ 1;
            const float a0[8] = {av0.x, av0.y, av0.z, av0.w, av1.x, av1.y, av1.z, av1.w};
#pragma unroll
            for (int j = 0; j < 8; j++) Ast[nxt][akh * 8 + j][arow_l] = f2tf32(a0[j]);
            uint4 p0 = make_uint4(f2tf32(wv0.x), f2tf32(wv0.y), f2tf32(wv0.z), f2tf32(wv0.w));
            uint4 p1 = make_uint4(f2tf32(wv1.x), f2tf32(wv1.y), f2tf32(wv1.z), f2tf32(wv1.w));
            *reinterpret_cast<uint4*>(&Bst[nxt][wk][wn4])     = p0;
            *reinterpret_cast<uint4*>(&Bst[nxt][wk + 8][wn4]) = p1;
            __syncthreads();
        }
    }

#pragma unroll
    for (int nf = 0; nf < 8; nf++) {
        int colb = bn + wn * 64 + nf * 8 + qt * 2;
        float b0 = bias ? bias[colb]     : 0.f;
        float b1 = bias ? bias[colb + 1] : 0.f;
#pragma unroll
        for (int mf = 0; mf < 2; mf++) {
            int row0 = bm + wm * 32 + mf * 16 + g;
            if (row0 < M) {
                float2 v = make_float2(acc[mf][nf][0] + b0, acc[mf][nf][1] + b1);
                *reinterpret_cast<float2*>(C + (size_t)row0 * N + colb) = v;
            }
            int row1 = row0 + 8;
            if (row1 < M) {
                float2 v = make_float2(acc[mf][nf][2] + b0, acc[mf][nf][3] + b1);
                *reinterpret_cast<float2*>(C + (size_t)row1 * N + colb) = v;
            }
        }
    }
}

// ---------------------------------------------------------------------------
// Persistent encoder recurrence v4.
// 128 blocks x 512 threads; block bi owns u in [bi*8, bi*8+8) (24 gate cols).
// 16 warps = 8 k-splits x 2 row-half warps. Thread microtile 4 rows x 3 cpairs.
// v4 changes vs v3:
//  - dense coalesced h loads (LDG.32, full 32B sectors: halves L1tex wf)
//  - h staged PRE-DUPLICATED (float2(h,h)) -> inner loop has NO dup MOVs:
//    2 LDS.128 + 3 LDS.64 + 12 fma2 per k  => fma2-pipe-bound
//  - grid-barrier fences executed by leader thread only (bar.sync gives
//    CTA-scope ordering; leader fence.gpu extends it — valid release chain)
// ---------------------------------------------------------------------------
#define ENC_BLOCKS 128
#define ENC_THREADS 512
#define WSH_FLOATS (1024 * 24)
#define HROW 132                  /* dup'd floats per k-row (64 rows x 2 + pad) */
#define HCH_FLOATS (8 * HROW)     /* one 8-k chunk */
#define HST_FLOATS (8 * 2 * HCH_FLOATS)
#define GHP_STRIDE 26
#define GHP_FLOATS (8 * 64 * GHP_STRIDE)
#define ENC_SMEM_FLOATS (WSH_FLOATS + HST_FLOATS + GHP_FLOATS)
#define ENC_SMEM_BYTES (ENC_SMEM_FLOATS * 4)

#define PAIRBAR(s) asm volatile("bar.sync %0, 64;" :: "r"(1 + (s)) : "memory")

__global__ __launch_bounds__(ENC_THREADS, 1) void enc_persistent(
    const float* __restrict__ gxe,   // [B*S][3U]  (includes b0)
    const float* __restrict__ Wh,    // [U][3U]
    const float* __restrict__ b1,    // [3U]
    float* __restrict__ enc_out,     // [B*S][U]
    unsigned* bar_cnt, unsigned* bar_rel)
{
    extern __shared__ float sm[];
    float* Wsh = sm;                           // [1024][24]
    float* hst = sm + WSH_FLOATS;              // [8 ksplit][2 buf][8 k][132]
    float* ghp = sm + WSH_FLOATS + HST_FLOATS; // [8 ksplit][64][26]

    const int tid  = threadIdx.x;
    const int wid  = tid >> 5;
    const int lane = tid & 31;
    const int s    = wid >> 1;        // ksplit 0..7
    const int wp   = wid & 1;         // row half 0..1
    const int rg   = lane >> 2;       // 0..7
    const int cg   = lane & 3;        // col-pair group
    const int bi   = blockIdx.x;
    const int u0   = bi * 8;
    const int ks   = s * 128;
    const int rbase = wp * 32 + rg * 4;

    // dense loader coords: 8 lanes cover 8 consecutive k of one row
    const int srow = wp * 32 + (lane >> 3);  // + j*4, j=0..7
    const int k_l  = lane & 7;

    float* hstS = hst + s * 2 * HCH_FLOATS;
    float* ghpS = ghp + s * 64 * GHP_STRIDE;

    for (int i = tid; i < WSH_FLOATS; i += ENC_THREADS) {
        int k = i / 24, c = i % 24;
        Wsh[i] = Wh[(size_t)k * G3 + (c >> 3) * UU + u0 + (c & 7)];
    }

    __shared__ unsigned relbase_s;
    if (tid == 0) relbase_s = *(volatile unsigned*)bar_rel;
    __syncthreads();
    const unsigned relbase = relbase_s;

    const int eb  = tid >> 3;
    const int edu = tid & 7;
    const int eu  = u0 + edu;
    const float b1z = b1[eu], b1r = b1[UU + eu], b1c = b1[2 * UU + eu];

    for (int t = 0; t < SS; t++) {
        if (t > 0) {
            // ---- grid barrier (leader-only fences) ----
            __syncthreads();
            if (tid == 0) {
                __threadfence();   // release: all block writes -> gpu scope
                unsigned old = atomicAdd(bar_cnt, 1u);
                if (old == ENC_BLOCKS - 1) {
                    atomicExch(bar_cnt, 0u);
                    atomicAdd(bar_rel, 1u);
                }
                while (*(volatile unsigned*)bar_rel - relbase < (unsigned)t) {}
                __threadfence();   // acquire
            }
            __syncthreads();

            float2 acc[4][3];
#pragma unroll
            for (int r = 0; r < 4; r++)
#pragma unroll
                for (int j = 0; j < 3; j++) acc[r][j] = make_float2(0.f, 0.f);

            const float* hbase = enc_out + (size_t)(t - 1) * UU + ks + k_l;
            float* h0 = hstS;
            float* h1 = hstS + HCH_FLOATS;

            float pf[8];
            // prologue: dense-load + dup-stage chunk 0
#pragma unroll
            for (int j = 0; j < 8; j++)
                pf[j] = hbase[(size_t)(srow + j * 4) * (SS * UU)];
#pragma unroll
            for (int j = 0; j < 8; j++)
                *reinterpret_cast<float2*>(&h0[k_l * HROW + (srow + j * 4) * 2]) =
                    make_float2(pf[j], pf[j]);
            PAIRBAR(s);

            for (int c = 0; c < 16; c++) {
                if (c + 1 < 16) {
#pragma unroll
                    for (int j = 0; j < 8; j++)
                        pf[j] = hbase[(size_t)(srow + j * 4) * (SS * UU) + (c + 1) * 8];
                }
                const float* hb = (c & 1) ? h1 : h0;
                const float* wb = Wsh + (size_t)(ks + c * 8) * 24 + cg * 6;
#pragma unroll
                for (int kk = 0; kk < 8; kk++) {
                    const float* hk = hb + kk * HROW + rbase * 2;
                    float4 ha = *reinterpret_cast<const float4*>(hk);
                    float4 hc = *reinterpret_cast<const float4*>(hk + 4);
                    const float* wr = wb + kk * 24;
                    float2 w0 = *reinterpret_cast<const float2*>(wr);
                    float2 w1 = *reinterpret_cast<const float2*>(wr + 2);
                    float2 w2 = *reinterpret_cast<const float2*>(wr + 4);
                    float2 d0 = make_float2(ha.x, ha.y);
                    float2 d1 = make_float2(ha.z, ha.w);
                    float2 d2 = make_float2(hc.x, hc.y);
                    float2 d3 = make_float2(hc.z, hc.w);
                    acc[0][0] = fma2(d0, w0, acc[0][0]);
                    acc[1][0] = fma2(d1, w0, acc[1][0]);
                    acc[2][0] = fma2(d2, w0, acc[2][0]);
                    acc[3][0] = fma2(d3, w0, acc[3][0]);
                    acc[0][1] = fma2(d0, w1, acc[0][1]);
                    acc[1][1] = fma2(d1, w1, acc[1][1]);
                    acc[2][1] = fma2(d2, w1, acc[2][1]);
                    acc[3][1] = fma2(d3, w1, acc[3][1]);
                    acc[0][2] = fma2(d0, w2, acc[0][2]);
                    acc[1][2] = fma2(d1, w2, acc[1][2]);
                    acc[2][2] = fma2(d2, w2, acc[2][2]);
                    acc[3][2] = fma2(d3, w2, acc[3][2]);
                }
                if (c + 1 < 16) {
                    float* hn = (c & 1) ? h0 : h1;
#pragma unroll
                    for (int j = 0; j < 8; j++)
                        *reinterpret_cast<float2*>(&hn[k_l * HROW + (srow + j * 4) * 2]) =
                            make_float2(pf[j], pf[j]);
                    PAIRBAR(s);
                }
            }

            // write partial gh for this ksplit
#pragma unroll
            for (int r = 0; r < 4; r++)
#pragma unroll
                for (int j = 0; j < 3; j++)
                    *reinterpret_cast<float2*>(
                        ghpS + (size_t)(rbase + r) * GHP_STRIDE + (cg * 3 + j) * 2) =
                        acc[r][j];
        }
        __syncthreads();

        // Epilogue: one (b,u) output per thread; reduce 8 ksplit partials
        {
            float ghz = 0.f, ghr = 0.f, ghc = 0.f, hold = 0.f;
            if (t > 0) {
#pragma unroll
                for (int s2 = 0; s2 < 8; s2++) {
                    const float* g = ghp + s2 * (64 * GHP_STRIDE) + eb * GHP_STRIDE;
                    ghz += g[edu];
                    ghr += g[8 + edu];
                    ghc += g[16 + edu];
                }
                hold = enc_out[(size_t)(eb * SS + t - 1) * UU + eu];
            }
            const float* gxrow = gxe + (size_t)(eb * SS + t) * G3;
            float z = sigmoidf_(gxrow[eu] + ghz + b1z);
            float r = sigmoidf_(gxrow[UU + eu] + ghr + b1r);
            float cc = tanhf(gxrow[2 * UU + eu] + r * (ghc + b1c));
            enc_out[(size_t)(eb * SS + t) * UU + eu] = z * hold + (1.f - z) * cc;
        }
    }
}

// ---------------------------------------------------------------------------
// Persistent decoder: ONE launch, 64 blocks (one per batch), all 39 steps.
// No inter-block dependency (attention/GRU are per-batch) -> no grid barrier.
// enc_out[b] (160KB) cached in smem; h carried in smem across steps.
// ---------------------------------------------------------------------------
#define DEC_SMEM_FLOATS (SS * UU + G3 + UU + 64)
#define DEC_SMEM_BYTES (DEC_SMEM_FLOATS * 4)

__global__ __launch_bounds__(256, 1) void dec_persistent(
    const float* __restrict__ enc_out,
    const float* __restrict__ P,
    const float* __restrict__ gxd,
    const float* __restrict__ db1,
    float* __restrict__ hdec)
{
    extern __shared__ float dsm[];
    float* enc_sh = dsm;                 // [40][1024]
    float* gxc    = dsm + SS * UU;       // [3072]
    float* h_sh   = gxc + G3;            // [1024]
    float* wsm    = h_sh + UU;           // [40]

    const int b   = blockIdx.x;
    const int tid = threadIdx.x;
    const int warp = tid >> 5, lane = tid & 31;

    // cache enc_out[b] (40x1024) in smem; init h = enc_out[b][S-1]
    {
        const float4* src = reinterpret_cast<const float4*>(enc_out + (size_t)b * SS * UU);
        float4* dst = reinterpret_cast<float4*>(enc_sh);
        for (int i = tid; i < SS * UU / 4; i += 256) dst[i] = src[i];
    }
    __syncthreads();
    for (int i = tid; i < UU; i += 256) h_sh[i] = enc_sh[(SS - 1) * UU + i];
    __syncthreads();

    const float* Pb = P + (size_t)b * SS * G3;

    for (int t = 0; t < TD; t++) {
        // Phase 1: attention scores (warp w -> s = w*5..w*5+4), all smem
        {
            float acc[5] = {0.f, 0.f, 0.f, 0.f, 0.f};
#pragma unroll 4
            for (int i = 0; i < 32; i++) {
                int uidx = lane + 32 * i;
                float hv = h_sh[uidx];
#pragma unroll
                for (int q = 0; q < 5; q++)
                    acc[q] += hv * enc_sh[(warp * 5 + q) * UU + uidx];
            }
#pragma unroll
            for (int q = 0; q < 5; q++) {
                float v = acc[q];
                for (int o = 16; o; o >>= 1) v += __shfl_xor_sync(0xffffffffu, v, o);
                if (lane == 0) wsm[warp * 5 + q] = v;
            }
        }
        __syncthreads();

        if (tid == 0) {
            float mx = -1e30f;
            for (int s = 0; s < SS; s++) mx = fmaxf(mx, wsm[s]);
            float smv = 0.f;
            for (int s = 0; s < SS; s++) { float e = expf(wsm[s] - mx); wsm[s] = e; smv += e; }
            float inv = 1.f / smv;
            for (int s = 0; s < SS; s++) wsm[s] *= inv;
        }
        __syncthreads();

        // Phase 2: gx_ctx = sum_s w_s * P[b,s,:]
        {
            float a[12];
#pragma unroll
            for (int i = 0; i < 12; i++) a[i] = 0.f;
            for (int s = 0; s < SS; s++) {
                float w = wsm[s];
                const float* row = Pb + (size_t)s * G3;
#pragma unroll
                for (int i = 0; i < 12; i++)
                    a[i] += w * row[tid + i * 256];
            }
#pragma unroll
            for (int i = 0; i < 12; i++) gxc[tid + i * 256] = a[i];
        }
        __syncthreads();

        // Phase 3: GRU(h0=0) -> h_new = (1-z)*c ; store to h_sh + hdec
        {
            const float* gx = gxd + (size_t)(b * TD + t) * G3;
            float* ho = hdec + (size_t)(b * TD + t) * UU;
#pragma unroll
            for (int i = 0; i < 4; i++) {
                int u = tid + i * 256;
                float z = sigmoidf_(gxc[u] + gx[u] + db1[u]);
                float r = sigmoidf_(gxc[UU + u] + gx[UU + u] + db1[UU + u]);
                float c = tanhf(gxc[2 * UU + u] + gx[2 * UU + u] + r * db1[2 * UU + u]);
                float hn = (1.f - z) * c;
                h_sh[u] = hn;
                ho[u] = hn;
            }
        }
        __syncthreads();
    }
}

// ---------------------------------------------------------------------------
extern "C" void kernel_launch(void* const* d_in, const int* in_sizes, int n_in,
                              void* d_out, int out_size)
{
    const int*   inp     = (const int*)d_in[0];
    const int*   targ    = (const int*)d_in[1];
    const float* enc_emb = (const float*)d_in[2];
    const float* enc_Wx  = (const float*)d_in[3];
    const float* enc_Wh  = (const float*)d_in[4];
    const float* enc_b   = (const float*)d_in[5];
    const float* dec_emb = (const float*)d_in[6];
    const float* dec_Wx  = (const float*)d_in[7];
    // d_in[8] = dec_Wh: provably unused (decoder GRU hidden input is zeros)
    const float* dec_b   = (const float*)d_in[9];
    const float* fc_W    = (const float*)d_in[10];
    const float* fc_b    = (const float*)d_in[11];
    float* out = (float*)d_out;

    float *gxe, *gxd, *enc_out, *P, *hdec;
    unsigned* bar;
    cudaGetSymbolAddress((void**)&gxe,     g_gxe);
    cudaGetSymbolAddress((void**)&gxd,     g_gxd);
    cudaGetSymbolAddress((void**)&enc_out, g_enc_out);
    cudaGetSymbolAddress((void**)&P,       g_P);
    cudaGetSymbolAddress((void**)&hdec,    g_hdec);
    cudaGetSymbolAddress((void**)&bar,     g_bar);

    cudaFuncSetAttribute(enc_persistent,
                         cudaFuncAttributeMaxDynamicSharedMemorySize, ENC_SMEM_BYTES);
    cudaFuncSetAttribute(dec_persistent,
                         cudaFuncAttributeMaxDynamicSharedMemorySize, DEC_SMEM_BYTES);

    // 1) Encoder gx (fp32 — feeds the recurrence, keep full precision)
    gemm_f32<<<dim3(G3 / 128, (BB * SS + 127) / 128), 256>>>(
        nullptr, enc_emb, inp, SS, SS, EE,
        enc_Wx, G3, enc_b, gxe, BB * SS, G3, EE);

    // 2) Decoder xt-part gx (tf32 tensor path)
    gemm_tf32<<<dim3(G3 / 128, (BB * TD + 127) / 128), 256>>>(
        nullptr, dec_emb, targ, TD, SS, EE,
        dec_Wx + (size_t)UU * G3, G3, dec_b, gxd, BB * TD, G3, EE);

    // 3) Encoder recurrence: persistent kernel v4
    enc_persistent<<<ENC_BLOCKS, ENC_THREADS, ENC_SMEM_BYTES>>>(
        gxe, enc_Wh, enc_b + G3, enc_out, bar, bar + 1);

    // 4) P = enc_out @ dec_Wx[:U]   (tf32 tensor path)
    gemm_tf32<<<dim3(G3 / 128, (BB * SS + 127) / 128), 256>>>(
        enc_out, nullptr, nullptr, 1, 1, UU,
        dec_Wx, G3, nullptr, P, BB * SS, G3, UU);

    // 5) Decoder recurrence: ONE persistent kernel (batch-parallel)
    dec_persistent<<<BB, 256, DEC_SMEM_BYTES>>>(
        enc_out, P, gxd, dec_b + G3, hdec);

    // 6) Batched output projection (tf32 tensor path)
    gemm_tf32<<<dim3(VV / 128, (BB * TD + 127) / 128), 256>>>(
        hdec, nullptr, nullptr, 1, 1, UU,
        fc_W, VV, fc_b, out, BB * TD, VV, UU);
}

// round 11
// speedup vs baseline: 1.7230x; 1.0139x over previous
#include <cuda_runtime.h>
#include <math.h>
#include <stdint.h>
#include <string.h>

#define BB 64
#define SS 40
#define TD 39
#define EE 256
#define UU 1024
#define VV 8192
#define G3 3072

// Scratch (device globals; no allocation allowed)
static __device__ float g_gxe[BB * SS * G3];      // encoder x@Wx + b0
static __device__ float g_gxd[BB * TD * G3];      // decoder xt@Wx_bot + b0
static __device__ float g_enc_out[BB * SS * UU];  // encoder hidden sequence
static __device__ float g_P[BB * SS * G3];        // enc_out @ dec_Wx[:U]
static __device__ float g_hdec[BB * TD * UU];     // decoder hidden per step
static __device__ unsigned g_bar[2];              // [0]=count, [1]=release epoch

// ---------------------------------------------------------------------------
__device__ __forceinline__ float2 fma2(float2 a, float2 b, float2 c) {
    unsigned long long ua, ub, uc;
    memcpy(&ua, &a, 8); memcpy(&ub, &b, 8); memcpy(&uc, &c, 8);
    asm("fma.rn.f32x2 %0, %1, %2, %0;" : "+l"(uc) : "l"(ua), "l"(ub));
    float2 r; memcpy(&r, &uc, 8);
    return r;
}

__device__ __forceinline__ float sigmoidf_(float x) {
    return 1.0f / (1.0f + expf(-x));
}

__device__ __forceinline__ uint32_t f2tf32(float x) {
    uint32_t r;
    asm("cvt.rna.tf32.f32 %0, %1;" : "=r"(r) : "f"(x));
    return r;
}

__device__ __forceinline__ void mma4(float c[4], const uint4& a,
                                     uint32_t b0, uint32_t b1) {
    asm("mma.sync.aligned.m16n8k8.row.col.f32.tf32.tf32.f32 "
        "{%0,%1,%2,%3},{%4,%5,%6,%7},{%8,%9},{%0,%1,%2,%3};"
        : "+f"(c[0]), "+f"(c[1]), "+f"(c[2]), "+f"(c[3])
        : "r"(a.x), "r"(a.y), "r"(a.z), "r"(a.w), "r"(b0), "r"(b1));
}

// ---------------------------------------------------------------------------
// fp32 GEMM (scalar f32x2 path) — step 1 only (feeds the recurrence).
// ---------------------------------------------------------------------------
__global__ __launch_bounds__(256, 2) void gemm_f32(
    const float* __restrict__ A,
    const float* __restrict__ emb, const int* __restrict__ idx,
    int idxTT, int idxStride, int lda,
    const float* __restrict__ W, int ldw,
    const float* __restrict__ bias,
    float* __restrict__ C, int M, int N, int K)
{
    __shared__ __align__(16) float As[2][8][128];
    __shared__ __align__(16) float Ws[2][8][128];

    const int tid = threadIdx.x;
    const int bm = blockIdx.y * 128;
    const int bn = blockIdx.x * 128;

    const int arow_l = tid & 127;
    const int akh    = tid >> 7;
    int mload = bm + arow_l;
    if (mload >= M) mload = M - 1;
    const float* arow;
    if (emb) {
        int r = idx[(mload / idxTT) * idxStride + (mload % idxTT)];
        arow = emb + (size_t)r * lda;
    } else {
        arow = A + (size_t)mload * lda;
    }

    const int wk = tid >> 5;
    const int wn = (tid & 31) * 4;
    const float* wptr = W + (size_t)wk * ldw + bn + wn;

    const int tx = tid & 15, ty = tid >> 4;
    const int r0 = ty * 8, c0 = tx * 8;

    float2 acc[8][4];
#pragma unroll
    for (int r = 0; r < 8; r++)
#pragma unroll
        for (int c = 0; c < 4; c++) acc[r][c] = make_float2(0.f, 0.f);

    const int nIter = K >> 3;

    float4 av = *reinterpret_cast<const float4*>(arow + akh * 4);
    float4 wv = *reinterpret_cast<const float4*>(wptr);
    As[0][akh * 4 + 0][arow_l] = av.x;
    As[0][akh * 4 + 1][arow_l] = av.y;
    As[0][akh * 4 + 2][arow_l] = av.z;
    As[0][akh * 4 + 3][arow_l] = av.w;
    *reinterpret_cast<float4*>(&Ws[0][wk][wn]) = wv;
    __syncthreads();

    for (int it = 0; it < nIter; it++) {
        const int cur = it & 1;
        if (it + 1 < nIter) {
            av = *reinterpret_cast<const float4*>(arow + (it + 1) * 8 + akh * 4);
            wv = *reinterpret_cast<const float4*>(wptr + (size_t)(it + 1) * 8 * ldw);
        }
#pragma unroll
        for (int k = 0; k < 8; k++) {
            float4 a0 = *reinterpret_cast<const float4*>(&As[cur][k][r0]);
            float4 a1 = *reinterpret_cast<const float4*>(&As[cur][k][r0 + 4]);
            float4 w0 = *reinterpret_cast<const float4*>(&Ws[cur][k][c0]);
            float4 w1 = *reinterpret_cast<const float4*>(&Ws[cur][k][c0 + 4]);
            float2 w[4];
            w[0] = make_float2(w0.x, w0.y);
            w[1] = make_float2(w0.z, w0.w);
            w[2] = make_float2(w1.x, w1.y);
            w[3] = make_float2(w1.z, w1.w);
            float ar[8] = {a0.x, a0.y, a0.z, a0.w, a1.x, a1.y, a1.z, a1.w};
#pragma unroll
            for (int r = 0; r < 8; r++) {
                float2 ad = make_float2(ar[r], ar[r]);
#pragma unroll
                for (int c = 0; c < 4; c++)
                    acc[r][c] = fma2(ad, w[c], acc[r][c]);
            }
        }
        if (it + 1 < nIter) {
            const int nxt = cur ^ 1;
            As[nxt][akh * 4 + 0][arow_l] = av.x;
            As[nxt][akh * 4 + 1][arow_l] = av.y;
            As[nxt][akh * 4 + 2][arow_l] = av.z;
            As[nxt][akh * 4 + 3][arow_l] = av.w;
            *reinterpret_cast<float4*>(&Ws[nxt][wk][wn]) = wv;
            __syncthreads();
        }
    }

    float bv[8];
#pragma unroll
    for (int j = 0; j < 8; j++) bv[j] = bias ? bias[bn + c0 + j] : 0.f;
#pragma unroll
    for (int r = 0; r < 8; r++) {
        int mrow = bm + r0 + r;
        if (mrow < M) {
            float4 o0, o1;
            o0.x = acc[r][0].x + bv[0];
            o0.y = acc[r][0].y + bv[1];
            o0.z = acc[r][1].x + bv[2];
            o0.w = acc[r][1].y + bv[3];
            o1.x = acc[r][2].x + bv[4];
            o1.y = acc[r][2].y + bv[5];
            o1.z = acc[r][3].x + bv[6];
            o1.w = acc[r][3].y + bv[7];
            *reinterpret_cast<float4*>(C + (size_t)mrow * N + bn + c0)     = o0;
            *reinterpret_cast<float4*>(C + (size_t)mrow * N + bn + c0 + 4) = o1;
        }
    }
}

// ---------------------------------------------------------------------------
// tf32 tensor-core GEMM v2 (mma.sync m16n8k8) — steps 2, 4, 6.
// Fragment-major smem staging: each thread's MMA operands are CONTIGUOUS.
// Per BK=16 iter per warp: 4 LDS.128 (A) + 8 LDS.128 (B) + 32 MMA
// (was 96 scalar LDS.32). Strides: A 3 float4/thread, B 5 float4/thread
// (odd -> conflict-free LDS.128 phases); regions offset by 8 words.
// ---------------------------------------------------------------------------
#define A_REG 392                 /* words per (k8,wm) region: 32*12 + 8 pad */
#define B_REG 648                 /* words per (k8,wn) region: 32*20 + 8 pad */
#define TF_A_WORDS (8 * A_REG)    /* 3136 */
#define TF_STAGE (TF_A_WORDS + 4 * B_REG)  /* 5728 words = 22.9 KB */

__global__ __launch_bounds__(256) void gemm_tf32(
    const float* __restrict__ A,
    const float* __restrict__ emb, const int* __restrict__ idx,
    int idxTT, int idxStride, int lda,
    const float* __restrict__ W, int ldw,
    const float* __restrict__ bias,
    float* __restrict__ C, int M, int N, int K)
{
    __shared__ __align__(16) uint32_t S[2 * TF_STAGE];

    const int tid  = threadIdx.x;
    const int lane = tid & 31;
    const int wid  = tid >> 5;
    const int wm   = wid & 3;
    const int wn   = wid >> 2;
    const int g    = lane >> 2;
    const int qt   = lane & 3;

    const int bm = blockIdx.y * 128;
    const int bn = blockIdx.x * 128;

    // A loader: row arow_l, k = akh*8 + j (j=0..7)
    const int arow_l = tid & 127;
    const int akh    = tid >> 7;
    int mload = bm + arow_l;
    if (mload >= M) mload = M - 1;
    const float* arow;
    if (emb) {
        int r = idx[(mload / idxTT) * idxStride + (mload % idxTT)];
        arow = emb + (size_t)r * lda;
    } else {
        arow = A + (size_t)mload * lda;
    }
    // loader's fragment-address constants
    const int l_wm = arow_l >> 5;
    const int l_mr = arow_l & 31;
    const int l_g  = l_mr & 7;
    const int l_hb = (l_mr >> 3) & 1;
    const int l_mf = (l_mr >> 4) & 1;
    const int aBase = (akh * 4 + l_wm) * A_REG;   // k8 == akh

    // W loader: k rows wk, wk+8; 4 cols at (tid&31)*4
    const int wk  = tid >> 5;
    const int wn4 = (tid & 31) * 4;
    const float* wptr = W + (size_t)wk * ldw + bn + wn4;
    const int b_qt = wk & 3, b_ks = wk >> 2;
    const int b_wn = wn4 >> 6;
    const int b_nf = (wn4 & 63) >> 3;
    // g for the 4 cols: (wn4&7)+cc, cc=0..3 (stays within one nf)
    const int b_g0 = wn4 & 7;

    float acc[2][8][4];
#pragma unroll
    for (int mf = 0; mf < 2; mf++)
#pragma unroll
        for (int nf = 0; nf < 8; nf++)
#pragma unroll
            for (int q = 0; q < 4; q++) acc[mf][nf][q] = 0.f;

    const int nIter = K >> 4;

    float4 av0 = *reinterpret_cast<const float4*>(arow + akh * 8);
    float4 av1 = *reinterpret_cast<const float4*>(arow + akh * 8 + 4);
    float4 wv0 = *reinterpret_cast<const float4*>(wptr);
    float4 wv1 = *reinterpret_cast<const float4*>(wptr + (size_t)8 * ldw);

    // --- stage tile 0 ---
    {
        float a8[8] = {av0.x, av0.y, av0.z, av0.w, av1.x, av1.y, av1.z, av1.w};
#pragma unroll
        for (int j = 0; j < 8; j++) {
            int jq = j & 3, jk = j >> 2;
            S[aBase + (l_g * 4 + jq) * 12 + l_mf * 4 + jk * 2 + l_hb] = f2tf32(a8[j]);
        }
        float b8[8] = {wv0.x, wv0.y, wv0.z, wv0.w, wv1.x, wv1.y, wv1.z, wv1.w};
#pragma unroll
        for (int kk = 0; kk < 2; kk++)
#pragma unroll
            for (int cc = 0; cc < 4; cc++)
                S[TF_A_WORDS + (kk * 2 + b_wn) * B_REG +
                  ((b_g0 + cc) * 4 + b_qt) * 20 + b_nf * 2 + b_ks] =
                    f2tf32(b8[kk * 4 + cc]);
    }
    __syncthreads();

    for (int it = 0; it < nIter; it++) {
        const int off = (it & 1) ? TF_STAGE : 0;
        if (it + 1 < nIter) {
            av0 = *reinterpret_cast<const float4*>(arow + (it + 1) * 16 + akh * 8);
            av1 = *reinterpret_cast<const float4*>(arow + (it + 1) * 16 + akh * 8 + 4);
            wv0 = *reinterpret_cast<const float4*>(wptr + (size_t)(it + 1) * 16 * ldw);
            wv1 = *reinterpret_cast<const float4*>(wptr + (size_t)((it + 1) * 16 + 8) * ldw);
        }
#pragma unroll
        for (int k8 = 0; k8 < 2; k8++) {
            const uint32_t* Ab = &S[off + (k8 * 4 + wm) * A_REG + lane * 12];
            uint4 aA = *reinterpret_cast<const uint4*>(Ab);
            uint4 aB = *reinterpret_cast<const uint4*>(Ab + 4);
            const uint32_t* Bb = &S[off + TF_A_WORDS + (k8 * 2 + wn) * B_REG + lane * 20];
            uint4 q0 = *reinterpret_cast<const uint4*>(Bb);
            uint4 q1 = *reinterpret_cast<const uint4*>(Bb + 4);
            uint4 q2 = *reinterpret_cast<const uint4*>(Bb + 8);
            uint4 q3 = *reinterpret_cast<const uint4*>(Bb + 12);
            mma4(acc[0][0], aA, q0.x, q0.y); mma4(acc[1][0], aB, q0.x, q0.y);
            mma4(acc[0][1], aA, q0.z, q0.w); mma4(acc[1][1], aB, q0.z, q0.w);
            mma4(acc[0][2], aA, q1.x, q1.y); mma4(acc[1][2], aB, q1.x, q1.y);
            mma4(acc[0][3], aA, q1.z, q1.w); mma4(acc[1][3], aB, q1.z, q1.w);
            mma4(acc[0][4], aA, q2.x, q2.y); mma4(acc[1][4], aB, q2.x, q2.y);
            mma4(acc[0][5], aA, q2.z, q2.w); mma4(acc[1][5], aB, q2.z, q2.w);
            mma4(acc[0][6], aA, q3.x, q3.y); mma4(acc[1][6], aB, q3.x, q3.y);
            mma4(acc[0][7], aA, q3.z, q3.w); mma4(acc[1][7], aB, q3.z, q3.w);
        }
        if (it + 1 < nIter) {
            const int noff = (it & 1) ? 0 : TF_STAGE;
            float a8[8] = {av0.x, av0.y, av0.z, av0.w, av1.x, av1.y, av1.z, av1.w};
#pragma unroll
            for (int j = 0; j < 8; j++) {
                int jq = j & 3, jk = j >> 2;
                S[noff + aBase + (l_g * 4 + jq) * 12 + l_mf * 4 + jk * 2 + l_hb] =
                    f2tf32(a8[j]);
            }
            float b8[8] = {wv0.x, wv0.y, wv0.z, wv0.w, wv1.x, wv1.y, wv1.z, wv1.w};
#pragma unroll
            for (int kk = 0; kk < 2; kk++)
#pragma unroll
                for (int cc = 0; cc < 4; cc++)
                    S[noff + TF_A_WORDS + (kk * 2 + b_wn) * B_REG +
                      ((b_g0 + cc) * 4 + b_qt) * 20 + b_nf * 2 + b_ks] =
                        f2tf32(b8[kk * 4 + cc]);
            __syncthreads();
        }
    }

    // Epilogue: c0,c1 -> (row g, cols qt*2, qt*2+1); c2,c3 -> row g+8
#pragma unroll
    for (int nf = 0; nf < 8; nf++) {
        int colb = bn + wn * 64 + nf * 8 + qt * 2;
        float b0 = bias ? bias[colb]     : 0.f;
        float b1 = bias ? bias[colb + 1] : 0.f;
#pragma unroll
        for (int mf = 0; mf < 2; mf++) {
            int row0 = bm + wm * 32 + mf * 16 + g;
            if (row0 < M) {
                float2 v = make_float2(acc[mf][nf][0] + b0, acc[mf][nf][1] + b1);
                *reinterpret_cast<float2*>(C + (size_t)row0 * N + colb) = v;
            }
            int row1 = row0 + 8;
            if (row1 < M) {
                float2 v = make_float2(acc[mf][nf][2] + b0, acc[mf][nf][3] + b1);
                *reinterpret_cast<float2*>(C + (size_t)row1 * N + colb) = v;
            }
        }
    }
}

// ---------------------------------------------------------------------------
// Persistent encoder recurrence v5: v4 + prefetch distance 2 (LDG issued two
// chunks ahead -> ~1100 cyc of cover vs ~600 cyc latency; zero exposure).
// ---------------------------------------------------------------------------
#define ENC_BLOCKS 128
#define ENC_THREADS 512
#define WSH_FLOATS (1024 * 24)
#define HROW 132
#define HCH_FLOATS (8 * HROW)
#define HST_FLOATS (8 * 2 * HCH_FLOATS)
#define GHP_STRIDE 26
#define GHP_FLOATS (8 * 64 * GHP_STRIDE)
#define ENC_SMEM_FLOATS (WSH_FLOATS + HST_FLOATS + GHP_FLOATS)
#define ENC_SMEM_BYTES (ENC_SMEM_FLOATS * 4)

#define PAIRBAR(s) asm volatile("bar.sync %0, 64;" :: "r"(1 + (s)) : "memory")

#define ENC_LOAD(pf, cidx)                                                     \
    _Pragma("unroll")                                                          \
    for (int j = 0; j < 8; j++)                                                \
        pf[j] = hbase[(size_t)(srow + j * 4) * (SS * UU) + (cidx) * 8];

#define ENC_STAGE(dst, pf)                                                     \
    _Pragma("unroll")                                                          \
    for (int j = 0; j < 8; j++)                                                \
        *reinterpret_cast<float2*>(&dst[k_l * HROW + (srow + j * 4) * 2]) =    \
            make_float2(pf[j], pf[j]);

#define ENC_COMPUTE(hb, cidx)                                                  \
    {                                                                          \
        const float* wb = Wsh + (size_t)(ks + (cidx) * 8) * 24 + cg * 6;       \
        _Pragma("unroll")                                                      \
        for (int kk = 0; kk < 8; kk++) {                                       \
            const float* hk = hb + kk * HROW + rbase * 2;                      \
            float4 ha = *reinterpret_cast<const float4*>(hk);                  \
            float4 hc = *reinterpret_cast<const float4*>(hk + 4);              \
            const float* wr = wb + kk * 24;                                    \
            float2 w0 = *reinterpret_cast<const float2*>(wr);                  \
            float2 w1 = *reinterpret_cast<const float2*>(wr + 2);              \
            float2 w2 = *reinterpret_cast<const float2*>(wr + 4);              \
            float2 d0 = make_float2(ha.x, ha.y);                               \
            float2 d1 = make_float2(ha.z, ha.w);                               \
            float2 d2 = make_float2(hc.x, hc.y);                               \
            float2 d3 = make_float2(hc.z, hc.w);                               \
            acc[0][0] = fma2(d0, w0, acc[0][0]);                               \
            acc[1][0] = fma2(d1, w0, acc[1][0]);                               \
            acc[2][0] = fma2(d2, w0, acc[2][0]);                               \
            acc[3][0] = fma2(d3, w0, acc[3][0]);                               \
            acc[0][1] = fma2(d0, w1, acc[0][1]);                               \
            acc[1][1] = fma2(d1, w1, acc[1][1]);                               \
            acc[2][1] = fma2(d2, w1, acc[2][1]);                               \
            acc[3][1] = fma2(d3, w1, acc[3][1]);                               \
            acc[0][2] = fma2(d0, w2, acc[0][2]);                               \
            acc[1][2] = fma2(d1, w2, acc[1][2]);                               \
            acc[2][2] = fma2(d2, w2, acc[2][2]);                               \
            acc[3][2] = fma2(d3, w2, acc[3][2]);                               \
        }                                                                      \
    }

__global__ __launch_bounds__(ENC_THREADS, 1) void enc_persistent(
    const float* __restrict__ gxe,   // [B*S][3U]  (includes b0)
    const float* __restrict__ Wh,    // [U][3U]
    const float* __restrict__ b1,    // [3U]
    float* __restrict__ enc_out,     // [B*S][U]
    unsigned* bar_cnt, unsigned* bar_rel)
{
    extern __shared__ float sm[];
    float* Wsh = sm;                           // [1024][24]
    float* hst = sm + WSH_FLOATS;              // [8 ksplit][2 buf][8 k][132]
    float* ghp = sm + WSH_FLOATS + HST_FLOATS; // [8 ksplit][64][26]

    const int tid  = threadIdx.x;
    const int wid  = tid >> 5;
    const int lane = tid & 31;
    const int s    = wid >> 1;
    const int wp   = wid & 1;
    const int rg   = lane >> 2;
    const int cg   = lane & 3;
    const int bi   = blockIdx.x;
    const int u0   = bi * 8;
    const int ks   = s * 128;
    const int rbase = wp * 32 + rg * 4;

    const int srow = wp * 32 + (lane >> 3);
    const int k_l  = lane & 7;

    float* hstS = hst + s * 2 * HCH_FLOATS;
    float* ghpS = ghp + s * 64 * GHP_STRIDE;

    for (int i = tid; i < WSH_FLOATS; i += ENC_THREADS) {
        int k = i / 24, c = i % 24;
        Wsh[i] = Wh[(size_t)k * G3 + (c >> 3) * UU + u0 + (c & 7)];
    }

    __shared__ unsigned relbase_s;
    if (tid == 0) relbase_s = *(volatile unsigned*)bar_rel;
    __syncthreads();
    const unsigned relbase = relbase_s;

    const int eb  = tid >> 3;
    const int edu = tid & 7;
    const int eu  = u0 + edu;
    const float b1z = b1[eu], b1r = b1[UU + eu], b1c = b1[2 * UU + eu];

    for (int t = 0; t < SS; t++) {
        if (t > 0) {
            __syncthreads();
            if (tid == 0) {
                __threadfence();
                unsigned old = atomicAdd(bar_cnt, 1u);
                if (old == ENC_BLOCKS - 1) {
                    atomicExch(bar_cnt, 0u);
                    atomicAdd(bar_rel, 1u);
                }
                while (*(volatile unsigned*)bar_rel - relbase < (unsigned)t) {}
                __threadfence();
            }
            __syncthreads();

            float2 acc[4][3];
#pragma unroll
            for (int r = 0; r < 4; r++)
#pragma unroll
                for (int j = 0; j < 3; j++) acc[r][j] = make_float2(0.f, 0.f);

            const float* hbase = enc_out + (size_t)(t - 1) * UU + ks + k_l;
            float* h0 = hstS;
            float* h1 = hstS + HCH_FLOATS;

            float pf0[8], pf1[8];
            ENC_LOAD(pf0, 0);
            ENC_STAGE(h0, pf0);
            ENC_LOAD(pf1, 1);
            PAIRBAR(s);

            for (int cp = 0; cp < 8; cp++) {
                int c0 = 2 * cp;
                // even chunk c0 (in h0); prefetch c0+2 into pf0
                if (c0 + 2 < 16) ENC_LOAD(pf0, c0 + 2);
                ENC_COMPUTE(h0, c0);
                ENC_STAGE(h1, pf1);   // chunk c0+1 always exists (c0<=14)
                PAIRBAR(s);
                // odd chunk c0+1 (in h1); prefetch c0+3 into pf1
                if (c0 + 3 < 16) ENC_LOAD(pf1, c0 + 3);
                ENC_COMPUTE(h1, c0 + 1);
                if (c0 + 2 < 16) {
                    ENC_STAGE(h0, pf0);
                    PAIRBAR(s);
                }
            }

            // write partial gh for this ksplit
#pragma unroll
            for (int r = 0; r < 4; r++)
#pragma unroll
                for (int j = 0; j < 3; j++)
                    *reinterpret_cast<float2*>(
                        ghpS + (size_t)(rbase + r) * GHP_STRIDE + (cg * 3 + j) * 2) =
                        acc[r][j];
        }
        __syncthreads();

        // Epilogue: one (b,u) output per thread; reduce 8 ksplit partials
        {
            float ghz = 0.f, ghr = 0.f, ghc = 0.f, hold = 0.f;
            if (t > 0) {
#pragma unroll
                for (int s2 = 0; s2 < 8; s2++) {
                    const float* g = ghp + s2 * (64 * GHP_STRIDE) + eb * GHP_STRIDE;
                    ghz += g[edu];
                    ghr += g[8 + edu];
                    ghc += g[16 + edu];
                }
                hold = enc_out[(size_t)(eb * SS + t - 1) * UU + eu];
            }
            const float* gxrow = gxe + (size_t)(eb * SS + t) * G3;
            float z = sigmoidf_(gxrow[eu] + ghz + b1z);
            float r = sigmoidf_(gxrow[UU + eu] + ghr + b1r);
            float cc = tanhf(gxrow[2 * UU + eu] + r * (ghc + b1c));
            enc_out[(size_t)(eb * SS + t) * UU + eu] = z * hold + (1.f - z) * cc;
        }
    }
}

// ---------------------------------------------------------------------------
// Persistent decoder: ONE launch, 64 blocks (one per batch), all 39 steps.
// ---------------------------------------------------------------------------
#define DEC_SMEM_FLOATS (SS * UU + G3 + UU + 64)
#define DEC_SMEM_BYTES (DEC_SMEM_FLOATS * 4)

__global__ __launch_bounds__(256, 1) void dec_persistent(
    const float* __restrict__ enc_out,
    const float* __restrict__ P,
    const float* __restrict__ gxd,
    const float* __restrict__ db1,
    float* __restrict__ hdec)
{
    extern __shared__ float dsm[];
    float* enc_sh = dsm;                 // [40][1024]
    float* gxc    = dsm + SS * UU;       // [3072]
    float* h_sh   = gxc + G3;            // [1024]
    float* wsm    = h_sh + UU;           // [40]

    const int b   = blockIdx.x;
    const int tid = threadIdx.x;
    const int warp = tid >> 5, lane = tid & 31;

    {
        const float4* src = reinterpret_cast<const float4*>(enc_out + (size_t)b * SS * UU);
        float4* dst = reinterpret_cast<float4*>(enc_sh);
        for (int i = tid; i < SS * UU / 4; i += 256) dst[i] = src[i];
    }
    __syncthreads();
    for (int i = tid; i < UU; i += 256) h_sh[i] = enc_sh[(SS - 1) * UU + i];
    __syncthreads();

    const float* Pb = P + (size_t)b * SS * G3;

    for (int t = 0; t < TD; t++) {
        {
            float acc[5] = {0.f, 0.f, 0.f, 0.f, 0.f};
#pragma unroll 4
            for (int i = 0; i < 32; i++) {
                int uidx = lane + 32 * i;
                float hv = h_sh[uidx];
#pragma unroll
                for (int q = 0; q < 5; q++)
                    acc[q] += hv * enc_sh[(warp * 5 + q) * UU + uidx];
            }
#pragma unroll
            for (int q = 0; q < 5; q++) {
                float v = acc[q];
                for (int o = 16; o; o >>= 1) v += __shfl_xor_sync(0xffffffffu, v, o);
                if (lane == 0) wsm[warp * 5 + q] = v;
            }
        }
        __syncthreads();

        if (tid == 0) {
            float mx = -1e30f;
            for (int s = 0; s < SS; s++) mx = fmaxf(mx, wsm[s]);
            float smv = 0.f;
            for (int s = 0; s < SS; s++) { float e = expf(wsm[s] - mx); wsm[s] = e; smv += e; }
            float inv = 1.f / smv;
            for (int s = 0; s < SS; s++) wsm[s] *= inv;
        }
        __syncthreads();

        {
            float a[12];
#pragma unroll
            for (int i = 0; i < 12; i++) a[i] = 0.f;
            for (int s = 0; s < SS; s++) {
                float w = wsm[s];
                const float* row = Pb + (size_t)s * G3;
#pragma unroll
                for (int i = 0; i < 12; i++)
                    a[i] += w * row[tid + i * 256];
            }
#pragma unroll
            for (int i = 0; i < 12; i++) gxc[tid + i * 256] = a[i];
        }
        __syncthreads();

        {
            const float* gx = gxd + (size_t)(b * TD + t) * G3;
            float* ho = hdec + (size_t)(b * TD + t) * UU;
#pragma unroll
            for (int i = 0; i < 4; i++) {
                int u = tid + i * 256;
                float z = sigmoidf_(gxc[u] + gx[u] + db1[u]);
                float r = sigmoidf_(gxc[UU + u] + gx[UU + u] + db1[UU + u]);
                float c = tanhf(gxc[2 * UU + u] + gx[2 * UU + u] + r * db1[2 * UU + u]);
                float hn = (1.f - z) * c;
                h_sh[u] = hn;
                ho[u] = hn;
            }
        }
        __syncthreads();
    }
}

// ---------------------------------------------------------------------------
extern "C" void kernel_launch(void* const* d_in, const int* in_sizes, int n_in,
                              void* d_out, int out_size)
{
    const int*   inp     = (const int*)d_in[0];
    const int*   targ    = (const int*)d_in[1];
    const float* enc_emb = (const float*)d_in[2];
    const float* enc_Wx  = (const float*)d_in[3];
    const float* enc_Wh  = (const float*)d_in[4];
    const float* enc_b   = (const float*)d_in[5];
    const float* dec_emb = (const float*)d_in[6];
    const float* dec_Wx  = (const float*)d_in[7];
    // d_in[8] = dec_Wh: provably unused (decoder GRU hidden input is zeros)
    const float* dec_b   = (const float*)d_in[9];
    const float* fc_W    = (const float*)d_in[10];
    const float* fc_b    = (const float*)d_in[11];
    float* out = (float*)d_out;

    float *gxe, *gxd, *enc_out, *P, *hdec;
    unsigned* bar;
    cudaGetSymbolAddress((void**)&gxe,     g_gxe);
    cudaGetSymbolAddress((void**)&gxd,     g_gxd);
    cudaGetSymbolAddress((void**)&enc_out, g_enc_out);
    cudaGetSymbolAddress((void**)&P,       g_P);
    cudaGetSymbolAddress((void**)&hdec,    g_hdec);
    cudaGetSymbolAddress((void**)&bar,     g_bar);

    cudaFuncSetAttribute(enc_persistent,
                         cudaFuncAttributeMaxDynamicSharedMemorySize, ENC_SMEM_BYTES);
    cudaFuncSetAttribute(dec_persistent,
                         cudaFuncAttributeMaxDynamicSharedMemorySize, DEC_SMEM_BYTES);

    // 1) Encoder gx (fp32 — feeds the recurrence, keep full precision)
    gemm_f32<<<dim3(G3 / 128, (BB * SS + 127) / 128), 256>>>(
        nullptr, enc_emb, inp, SS, SS, EE,
        enc_Wx, G3, enc_b, gxe, BB * SS, G3, EE);

    // 2) Decoder xt-part gx (tf32 tensor path)
    gemm_tf32<<<dim3(G3 / 128, (BB * TD + 127) / 128), 256>>>(
        nullptr, dec_emb, targ, TD, SS, EE,
        dec_Wx + (size_t)UU * G3, G3, dec_b, gxd, BB * TD, G3, EE);

    // 3) Encoder recurrence: persistent kernel v5
    enc_persistent<<<ENC_BLOCKS, ENC_THREADS, ENC_SMEM_BYTES>>>(
        gxe, enc_Wh, enc_b + G3, enc_out, bar, bar + 1);

    // 4) P = enc_out @ dec_Wx[:U]   (tf32 tensor path)
    gemm_tf32<<<dim3(G3 / 128, (BB * SS + 127) / 128), 256>>>(
        enc_out, nullptr, nullptr, 1, 1, UU,
        dec_Wx, G3, nullptr, P, BB * SS, G3, UU);

    // 5) Decoder recurrence: ONE persistent kernel (batch-parallel)
    dec_persistent<<<BB, 256, DEC_SMEM_BYTES>>>(
        enc_out, P, gxd, dec_b + G3, hdec);

    // 6) Batched output projection (tf32 tensor path)
    gemm_tf32<<<dim3(VV / 128, (BB * TD + 127) / 128), 256>>>(
        hdec, nullptr, nullptr, 1, 1, UU,
        fc_W, VV, fc_b, out, BB * TD, VV, UU);
}

// round 12
// speedup vs baseline: 1.8544x; 1.0763x over previous
#include <cuda_runtime.h>
#include <math.h>
#include <stdint.h>
#include <string.h>

#define BB 64
#define SS 40
#define TD 39
#define EE 256
#define UU 1024
#define VV 8192
#define G3 3072

// Scratch (device globals; no allocation allowed)
static __device__ float g_gxe[BB * SS * G3];      // encoder x@Wx + b0
static __device__ float g_gxd[BB * TD * G3];      // decoder xt@Wx_bot + b0
static __device__ float g_enc_out[BB * SS * UU];  // encoder hidden sequence
static __device__ float g_P[BB * SS * G3];        // enc_out @ dec_Wx[:U]
static __device__ float g_hdec[BB * TD * UU];     // decoder hidden per step
static __device__ unsigned g_bar[2];              // [0]=count, [1]=release epoch

// ---------------------------------------------------------------------------
__device__ __forceinline__ float2 fma2(float2 a, float2 b, float2 c) {
    unsigned long long ua, ub, uc;
    memcpy(&ua, &a, 8); memcpy(&ub, &b, 8); memcpy(&uc, &c, 8);
    asm("fma.rn.f32x2 %0, %1, %2, %0;" : "+l"(uc) : "l"(ua), "l"(ub));
    float2 r; memcpy(&r, &uc, 8);
    return r;
}

__device__ __forceinline__ float sigmoidf_(float x) {
    return 1.0f / (1.0f + expf(-x));
}

__device__ __forceinline__ uint32_t f2tf32(float x) {
    uint32_t r;
    asm("cvt.rna.tf32.f32 %0, %1;" : "=r"(r) : "f"(x));
    return r;
}

__device__ __forceinline__ void mma4(float c[4], const uint4& a,
                                     uint32_t b0, uint32_t b1) {
    asm("mma.sync.aligned.m16n8k8.row.col.f32.tf32.tf32.f32 "
        "{%0,%1,%2,%3},{%4,%5,%6,%7},{%8,%9},{%0,%1,%2,%3};"
        : "+f"(c[0]), "+f"(c[1]), "+f"(c[2]), "+f"(c[3])
        : "r"(a.x), "r"(a.y), "r"(a.z), "r"(a.w), "r"(b0), "r"(b1));
}

// ---------------------------------------------------------------------------
// fp32 GEMM (scalar f32x2 path) — step 1 only (feeds the recurrence).
// ---------------------------------------------------------------------------
__global__ __launch_bounds__(256, 2) void gemm_f32(
    const float* __restrict__ A,
    const float* __restrict__ emb, const int* __restrict__ idx,
    int idxTT, int idxStride, int lda,
    const float* __restrict__ W, int ldw,
    const float* __restrict__ bias,
    float* __restrict__ C, int M, int N, int K)
{
    __shared__ __align__(16) float As[2][8][128];
    __shared__ __align__(16) float Ws[2][8][128];

    const int tid = threadIdx.x;
    const int bm = blockIdx.y * 128;
    const int bn = blockIdx.x * 128;

    const int arow_l = tid & 127;
    const int akh    = tid >> 7;
    int mload = bm + arow_l;
    if (mload >= M) mload = M - 1;
    const float* arow;
    if (emb) {
        int r = idx[(mload / idxTT) * idxStride + (mload % idxTT)];
        arow = emb + (size_t)r * lda;
    } else {
        arow = A + (size_t)mload * lda;
    }

    const int wk = tid >> 5;
    const int wn = (tid & 31) * 4;
    const float* wptr = W + (size_t)wk * ldw + bn + wn;

    const int tx = tid & 15, ty = tid >> 4;
    const int r0 = ty * 8, c0 = tx * 8;

    float2 acc[8][4];
#pragma unroll
    for (int r = 0; r < 8; r++)
#pragma unroll
        for (int c = 0; c < 4; c++) acc[r][c] = make_float2(0.f, 0.f);

    const int nIter = K >> 3;

    float4 av = *reinterpret_cast<const float4*>(arow + akh * 4);
    float4 wv = *reinterpret_cast<const float4*>(wptr);
    As[0][akh * 4 + 0][arow_l] = av.x;
    As[0][akh * 4 + 1][arow_l] = av.y;
    As[0][akh * 4 + 2][arow_l] = av.z;
    As[0][akh * 4 + 3][arow_l] = av.w;
    *reinterpret_cast<float4*>(&Ws[0][wk][wn]) = wv;
    __syncthreads();

    for (int it = 0; it < nIter; it++) {
        const int cur = it & 1;
        if (it + 1 < nIter) {
            av = *reinterpret_cast<const float4*>(arow + (it + 1) * 8 + akh * 4);
            wv = *reinterpret_cast<const float4*>(wptr + (size_t)(it + 1) * 8 * ldw);
        }
#pragma unroll
        for (int k = 0; k < 8; k++) {
            float4 a0 = *reinterpret_cast<const float4*>(&As[cur][k][r0]);
            float4 a1 = *reinterpret_cast<const float4*>(&As[cur][k][r0 + 4]);
            float4 w0 = *reinterpret_cast<const float4*>(&Ws[cur][k][c0]);
            float4 w1 = *reinterpret_cast<const float4*>(&Ws[cur][k][c0 + 4]);
            float2 w[4];
            w[0] = make_float2(w0.x, w0.y);
            w[1] = make_float2(w0.z, w0.w);
            w[2] = make_float2(w1.x, w1.y);
            w[3] = make_float2(w1.z, w1.w);
            float ar[8] = {a0.x, a0.y, a0.z, a0.w, a1.x, a1.y, a1.z, a1.w};
#pragma unroll
            for (int r = 0; r < 8; r++) {
                float2 ad = make_float2(ar[r], ar[r]);
#pragma unroll
                for (int c = 0; c < 4; c++)
                    acc[r][c] = fma2(ad, w[c], acc[r][c]);
            }
        }
        if (it + 1 < nIter) {
            const int nxt = cur ^ 1;
            As[nxt][akh * 4 + 0][arow_l] = av.x;
            As[nxt][akh * 4 + 1][arow_l] = av.y;
            As[nxt][akh * 4 + 2][arow_l] = av.z;
            As[nxt][akh * 4 + 3][arow_l] = av.w;
            *reinterpret_cast<float4*>(&Ws[nxt][wk][wn]) = wv;
            __syncthreads();
        }
    }

    float bv[8];
#pragma unroll
    for (int j = 0; j < 8; j++) bv[j] = bias ? bias[bn + c0 + j] : 0.f;
#pragma unroll
    for (int r = 0; r < 8; r++) {
        int mrow = bm + r0 + r;
        if (mrow < M) {
            float4 o0, o1;
            o0.x = acc[r][0].x + bv[0];
            o0.y = acc[r][0].y + bv[1];
            o0.z = acc[r][1].x + bv[2];
            o0.w = acc[r][1].y + bv[3];
            o1.x = acc[r][2].x + bv[4];
            o1.y = acc[r][2].y + bv[5];
            o1.z = acc[r][3].x + bv[6];
            o1.w = acc[r][3].y + bv[7];
            *reinterpret_cast<float4*>(C + (size_t)mrow * N + bn + c0)     = o0;
            *reinterpret_cast<float4*>(C + (size_t)mrow * N + bn + c0 + 4) = o1;
        }
    }
}

// ---------------------------------------------------------------------------
// tf32 tensor-core GEMM v2 (mma.sync m16n8k8) — steps 2, 4, 6.
// ---------------------------------------------------------------------------
#define A_REG 392
#define B_REG 648
#define TF_A_WORDS (8 * A_REG)
#define TF_STAGE (TF_A_WORDS + 4 * B_REG)

__global__ __launch_bounds__(256) void gemm_tf32(
    const float* __restrict__ A,
    const float* __restrict__ emb, const int* __restrict__ idx,
    int idxTT, int idxStride, int lda,
    const float* __restrict__ W, int ldw,
    const float* __restrict__ bias,
    float* __restrict__ C, int M, int N, int K)
{
    __shared__ __align__(16) uint32_t S[2 * TF_STAGE];

    const int tid  = threadIdx.x;
    const int lane = tid & 31;
    const int wid  = tid >> 5;
    const int wm   = wid & 3;
    const int wn   = wid >> 2;
    const int g    = lane >> 2;
    const int qt   = lane & 3;

    const int bm = blockIdx.y * 128;
    const int bn = blockIdx.x * 128;

    const int arow_l = tid & 127;
    const int akh    = tid >> 7;
    int mload = bm + arow_l;
    if (mload >= M) mload = M - 1;
    const float* arow;
    if (emb) {
        int r = idx[(mload / idxTT) * idxStride + (mload % idxTT)];
        arow = emb + (size_t)r * lda;
    } else {
        arow = A + (size_t)mload * lda;
    }
    const int l_wm = arow_l >> 5;
    const int l_mr = arow_l & 31;
    const int l_g  = l_mr & 7;
    const int l_hb = (l_mr >> 3) & 1;
    const int l_mf = (l_mr >> 4) & 1;
    const int aBase = (akh * 4 + l_wm) * A_REG;

    const int wk  = tid >> 5;
    const int wn4 = (tid & 31) * 4;
    const float* wptr = W + (size_t)wk * ldw + bn + wn4;
    const int b_qt = wk & 3, b_ks = wk >> 2;
    const int b_wn = wn4 >> 6;
    const int b_nf = (wn4 & 63) >> 3;
    const int b_g0 = wn4 & 7;

    float acc[2][8][4];
#pragma unroll
    for (int mf = 0; mf < 2; mf++)
#pragma unroll
        for (int nf = 0; nf < 8; nf++)
#pragma unroll
            for (int q = 0; q < 4; q++) acc[mf][nf][q] = 0.f;

    const int nIter = K >> 4;

    float4 av0 = *reinterpret_cast<const float4*>(arow + akh * 8);
    float4 av1 = *reinterpret_cast<const float4*>(arow + akh * 8 + 4);
    float4 wv0 = *reinterpret_cast<const float4*>(wptr);
    float4 wv1 = *reinterpret_cast<const float4*>(wptr + (size_t)8 * ldw);

    {
        float a8[8] = {av0.x, av0.y, av0.z, av0.w, av1.x, av1.y, av1.z, av1.w};
#pragma unroll
        for (int j = 0; j < 8; j++) {
            int jq = j & 3, jk = j >> 2;
            S[aBase + (l_g * 4 + jq) * 12 + l_mf * 4 + jk * 2 + l_hb] = f2tf32(a8[j]);
        }
        float b8[8] = {wv0.x, wv0.y, wv0.z, wv0.w, wv1.x, wv1.y, wv1.z, wv1.w};
#pragma unroll
        for (int kk = 0; kk < 2; kk++)
#pragma unroll
            for (int cc = 0; cc < 4; cc++)
                S[TF_A_WORDS + (kk * 2 + b_wn) * B_REG +
                  ((b_g0 + cc) * 4 + b_qt) * 20 + b_nf * 2 + b_ks] =
                    f2tf32(b8[kk * 4 + cc]);
    }
    __syncthreads();

    for (int it = 0; it < nIter; it++) {
        const int off = (it & 1) ? TF_STAGE : 0;
        if (it + 1 < nIter) {
            av0 = *reinterpret_cast<const float4*>(arow + (it + 1) * 16 + akh * 8);
            av1 = *reinterpret_cast<const float4*>(arow + (it + 1) * 16 + akh * 8 + 4);
            wv0 = *reinterpret_cast<const float4*>(wptr + (size_t)(it + 1) * 16 * ldw);
            wv1 = *reinterpret_cast<const float4*>(wptr + (size_t)((it + 1) * 16 + 8) * ldw);
        }
#pragma unroll
        for (int k8 = 0; k8 < 2; k8++) {
            const uint32_t* Ab = &S[off + (k8 * 4 + wm) * A_REG + lane * 12];
            uint4 aA = *reinterpret_cast<const uint4*>(Ab);
            uint4 aB = *reinterpret_cast<const uint4*>(Ab + 4);
            const uint32_t* Bb = &S[off + TF_A_WORDS + (k8 * 2 + wn) * B_REG + lane * 20];
            uint4 q0 = *reinterpret_cast<const uint4*>(Bb);
            uint4 q1 = *reinterpret_cast<const uint4*>(Bb + 4);
            uint4 q2 = *reinterpret_cast<const uint4*>(Bb + 8);
            uint4 q3 = *reinterpret_cast<const uint4*>(Bb + 12);
            mma4(acc[0][0], aA, q0.x, q0.y); mma4(acc[1][0], aB, q0.x, q0.y);
            mma4(acc[0][1], aA, q0.z, q0.w); mma4(acc[1][1], aB, q0.z, q0.w);
            mma4(acc[0][2], aA, q1.x, q1.y); mma4(acc[1][2], aB, q1.x, q1.y);
            mma4(acc[0][3], aA, q1.z, q1.w); mma4(acc[1][3], aB, q1.z, q1.w);
            mma4(acc[0][4], aA, q2.x, q2.y); mma4(acc[1][4], aB, q2.x, q2.y);
            mma4(acc[0][5], aA, q2.z, q2.w); mma4(acc[1][5], aB, q2.z, q2.w);
            mma4(acc[0][6], aA, q3.x, q3.y); mma4(acc[1][6], aB, q3.x, q3.y);
            mma4(acc[0][7], aA, q3.z, q3.w); mma4(acc[1][7], aB, q3.z, q3.w);
        }
        if (it + 1 < nIter) {
            const int noff = (it & 1) ? 0 : TF_STAGE;
            float a8[8] = {av0.x, av0.y, av0.z, av0.w, av1.x, av1.y, av1.z, av1.w};
#pragma unroll
            for (int j = 0; j < 8; j++) {
                int jq = j & 3, jk = j >> 2;
                S[noff + aBase + (l_g * 4 + jq) * 12 + l_mf * 4 + jk * 2 + l_hb] =
                    f2tf32(a8[j]);
            }
            float b8[8] = {wv0.x, wv0.y, wv0.z, wv0.w, wv1.x, wv1.y, wv1.z, wv1.w};
#pragma unroll
            for (int kk = 0; kk < 2; kk++)
#pragma unroll
                for (int cc = 0; cc < 4; cc++)
                    S[noff + TF_A_WORDS + (kk * 2 + b_wn) * B_REG +
                      ((b_g0 + cc) * 4 + b_qt) * 20 + b_nf * 2 + b_ks] =
                        f2tf32(b8[kk * 4 + cc]);
            __syncthreads();
        }
    }

#pragma unroll
    for (int nf = 0; nf < 8; nf++) {
        int colb = bn + wn * 64 + nf * 8 + qt * 2;
        float b0 = bias ? bias[colb]     : 0.f;
        float b1 = bias ? bias[colb + 1] : 0.f;
#pragma unroll
        for (int mf = 0; mf < 2; mf++) {
            int row0 = bm + wm * 32 + mf * 16 + g;
            if (row0 < M) {
                float2 v = make_float2(acc[mf][nf][0] + b0, acc[mf][nf][1] + b1);
                *reinterpret_cast<float2*>(C + (size_t)row0 * N + colb) = v;
            }
            int row1 = row0 + 8;
            if (row1 < M) {
                float2 v = make_float2(acc[mf][nf][2] + b0, acc[mf][nf][3] + b1);
                *reinterpret_cast<float2*>(C + (size_t)row1 * N + colb) = v;
            }
        }
    }
}

// ---------------------------------------------------------------------------
// Persistent encoder recurrence v6: TENSOR-CORE (tf32 Dekker-split, fp32-
// equivalent accuracy). 128 blocks x 256 threads; block bi owns 24 gate cols
// (u in [bi*8, bi*8+8) x 3 gates). 8 warps = 8 k-splits (128 k each; 16
// 8k-chunks). Per chunk per warp: h staged hi/lo fragment-major in smem
// (warp-private, __syncwarp only), W fragments LDG'd from L2 with on-the-fly
// split, 36 HMMA (4 m-tiles x 3 n-tiles x 3 split terms).
// gh = h_hi@W_hi + h_hi@W_lo + h_lo@W_hi  (error ~2^-22: fp32-equivalent).
// Partials reduced across 8 warps via smem; GRU epilogue unchanged.
// ---------------------------------------------------------------------------
#define ENC_BLOCKS 128
#define ENC_THREADS 256
#define EWARPS 8
#define ACH 1024                          /* words per chunk buf (hi512+lo512) */
#define ENC_STG_WORDS (EWARPS * 2 * ACH)  /* 16384 */
#define GHP_ST 26
#define GHP_WORDS (EWARPS * 64 * GHP_ST)  /* 13312 */
#define ENC_SMEM_BYTES ((ENC_STG_WORDS + GHP_WORDS) * 4)

#define ELOADH(pf, cidx)                                                      \
    _Pragma("unroll")                                                         \
    for (int it = 0; it < 8; it++)                                            \
        pf[it] = *reinterpret_cast<const float2*>(                            \
            hb2 + (size_t)(it * 8 + g) * (SS * UU) + (cidx) * 8);

#define ESTAGE(bp, pf)                                                        \
    _Pragma("unroll")                                                         \
    for (int it = 0; it < 8; it++) {                                          \
        uint32_t h0 = f2tf32(pf[it].x);                                       \
        uint32_t l0 = f2tf32(pf[it].x - __uint_as_float(h0));                 \
        uint32_t h1 = f2tf32(pf[it].y);                                       \
        uint32_t l1 = f2tf32(pf[it].y - __uint_as_float(h1));                 \
        int wi = (it >> 1) * 128 + (it & 1) + sbase;                          \
        bp[wi] = h0; bp[wi + 4] = h1;                                         \
        bp[512 + wi] = l0; bp[512 + wi + 4] = l1;                             \
    }

#define ELOADB(wb, cidx)                                                      \
    {                                                                         \
        const float* wp_ = wB + (size_t)(cidx) * (8 * G3);                    \
        wb[0] = wp_[0];      wb[1] = wp_[4 * G3];                             \
        wb[2] = wp_[UU];     wb[3] = wp_[UU + 4 * G3];                        \
        wb[4] = wp_[2 * UU]; wb[5] = wp_[2 * UU + 4 * G3];                    \
    }

#define ECONSUME(bp, wb)                                                      \
    {                                                                         \
        uint4 aH[4], aL[4];                                                   \
        _Pragma("unroll")                                                     \
        for (int mt = 0; mt < 4; mt++) {                                      \
            aH[mt] = *reinterpret_cast<const uint4*>(bp + mt * 128 + lane * 4);\
            aL[mt] = *reinterpret_cast<const uint4*>(bp + 512 + mt * 128 + lane * 4);\
        }                                                                     \
        _Pragma("unroll")                                                     \
        for (int nf = 0; nf < 3; nf++) {                                      \
            uint32_t p0h = f2tf32(wb[2 * nf]);                                \
            uint32_t p0l = f2tf32(wb[2 * nf] - __uint_as_float(p0h));         \
            uint32_t p1h = f2tf32(wb[2 * nf + 1]);                            \
            uint32_t p1l = f2tf32(wb[2 * nf + 1] - __uint_as_float(p1h));     \
            _Pragma("unroll")                                                 \
            for (int mt = 0; mt < 4; mt++) {                                  \
                mma4(acc[mt][nf], aH[mt], p0h, p1h);                          \
                mma4(acc[mt][nf], aH[mt], p0l, p1l);                          \
                mma4(acc[mt][nf], aL[mt], p0h, p1h);                          \
            }                                                                 \
        }                                                                     \
    }

__global__ __launch_bounds__(ENC_THREADS, 1) void enc_persistent(
    const float* __restrict__ gxe,   // [B*S][3U]  (includes b0)
    const float* __restrict__ Wh,    // [U][3U]
    const float* __restrict__ b1,    // [3U]
    float* __restrict__ enc_out,     // [B*S][U]
    unsigned* bar_cnt, unsigned* bar_rel)
{
    extern __shared__ float sm[];
    uint32_t* stg = reinterpret_cast<uint32_t*>(sm);   // [8 warps][2][1024]
    float* ghp = sm + ENC_STG_WORDS;                   // [8 warps][64][26]

    const int tid  = threadIdx.x;
    const int w    = tid >> 5;
    const int lane = tid & 31;
    const int g    = lane >> 2;       // 0..7
    const int qt   = lane & 3;        // 0..3
    const int bi   = blockIdx.x;
    const int u0   = bi * 8;

    // stager lane coords: kofs = kh*4 + qh*2 (float2 -> k, k+1)
    const int lqh  = lane & 1;
    const int lkh  = (lane >> 1) & 1;
    const int kofs = lkh * 4 + lqh * 2;
    const int sbase = g * 16 + lqh * 8 + lkh * 2;

    uint32_t* buf0 = stg + w * 2 * ACH;
    uint32_t* buf1 = buf0 + ACH;
    float* ghpW = ghp + w * 64 * GHP_ST;

    // B base: Wh[(w*128 + qt)*G3 + u0 + g]
    const float* wB = Wh + (size_t)(w * 128 + qt) * G3 + u0 + g;

    __shared__ unsigned relbase_s;
    if (tid == 0) relbase_s = *(volatile unsigned*)bar_rel;
    __syncthreads();
    const unsigned relbase = relbase_s;

    // epilogue constants
    const int edu = tid & 7;
    const int eu  = u0 + edu;
    const float b1z = b1[eu], b1r = b1[UU + eu], b1c = b1[2 * UU + eu];

    for (int t = 0; t < SS; t++) {
        if (t > 0) {
            // ---- grid barrier (leader-only fences) ----
            __syncthreads();
            if (tid == 0) {
                __threadfence();
                unsigned old = atomicAdd(bar_cnt, 1u);
                if (old == ENC_BLOCKS - 1) {
                    atomicExch(bar_cnt, 0u);
                    atomicAdd(bar_rel, 1u);
                }
                while (*(volatile unsigned*)bar_rel - relbase < (unsigned)t) {}
                __threadfence();
            }
            __syncthreads();

            float acc[4][3][4];
#pragma unroll
            for (int mt = 0; mt < 4; mt++)
#pragma unroll
                for (int nf = 0; nf < 3; nf++)
#pragma unroll
                    for (int q = 0; q < 4; q++) acc[mt][nf][q] = 0.f;

            const float* hb2 = enc_out + (size_t)(t - 1) * UU + w * 128 + kofs;

            float2 pf0[8], pf1[8];
            float wb0[6], wb1[6];

            ELOADH(pf0, 0); ELOADB(wb0, 0);
            ELOADH(pf1, 1); ELOADB(wb1, 1);
            ESTAGE(buf0, pf0);
            __syncwarp();

            for (int cp = 0; cp < 8; cp++) {
                const int c0 = 2 * cp;
                if (c0 + 2 < 16) ELOADH(pf0, c0 + 2);
                ECONSUME(buf0, wb0);             // chunk c0
                if (c0 + 2 < 16) ELOADB(wb0, c0 + 2);
                ESTAGE(buf1, pf1);               // stage chunk c0+1
                __syncwarp();
                if (c0 + 3 < 16) ELOADH(pf1, c0 + 3);
                ECONSUME(buf1, wb1);             // chunk c0+1
                if (c0 + 3 < 16) ELOADB(wb1, c0 + 3);
                if (c0 + 2 < 16) {
                    ESTAGE(buf0, pf0);           // stage chunk c0+2
                    __syncwarp();
                }
            }

            // write this warp's partial gh
#pragma unroll
            for (int mt = 0; mt < 4; mt++)
#pragma unroll
                for (int nf = 0; nf < 3; nf++) {
                    int r0 = mt * 16 + g;
                    float* dst = ghpW + r0 * GHP_ST + nf * 8 + qt * 2;
                    *reinterpret_cast<float2*>(dst) =
                        make_float2(acc[mt][nf][0], acc[mt][nf][1]);
                    *reinterpret_cast<float2*>(dst + 8 * GHP_ST) =
                        make_float2(acc[mt][nf][2], acc[mt][nf][3]);
                }
        }
        __syncthreads();

        // Epilogue: 2 (b,u) outputs per thread; reduce 8 warp partials
#pragma unroll
        for (int i = 0; i < 2; i++) {
            int b = (tid >> 3) + i * 32;
            float ghz = 0.f, ghr = 0.f, ghc = 0.f, hold = 0.f;
            if (t > 0) {
#pragma unroll
                for (int w2 = 0; w2 < EWARPS; w2++) {
                    const float* gg = ghp + w2 * (64 * GHP_ST) + b * GHP_ST;
                    ghz += gg[edu];
                    ghr += gg[8 + edu];
                    ghc += gg[16 + edu];
                }
                hold = enc_out[(size_t)(b * SS + t - 1) * UU + eu];
            }
            const float* gxrow = gxe + (size_t)(b * SS + t) * G3;
            float z = sigmoidf_(gxrow[eu] + ghz + b1z);
            float r = sigmoidf_(gxrow[UU + eu] + ghr + b1r);
            float cc = tanhf(gxrow[2 * UU + eu] + r * (ghc + b1c));
            enc_out[(size_t)(b * SS + t) * UU + eu] = z * hold + (1.f - z) * cc;
        }
    }
}

// ---------------------------------------------------------------------------
// Persistent decoder: ONE launch, 64 blocks (one per batch), all 39 steps.
// ---------------------------------------------------------------------------
#define DEC_SMEM_FLOATS (SS * UU + G3 + UU + 64)
#define DEC_SMEM_BYTES (DEC_SMEM_FLOATS * 4)

__global__ __launch_bounds__(256, 1) void dec_persistent(
    const float* __restrict__ enc_out,
    const float* __restrict__ P,
    const float* __restrict__ gxd,
    const float* __restrict__ db1,
    float* __restrict__ hdec)
{
    extern __shared__ float dsm[];
    float* enc_sh = dsm;
    float* gxc    = dsm + SS * UU;
    float* h_sh   = gxc + G3;
    float* wsm    = h_sh + UU;

    const int b   = blockIdx.x;
    const int tid = threadIdx.x;
    const int warp = tid >> 5, lane = tid & 31;

    {
        const float4* src = reinterpret_cast<const float4*>(enc_out + (size_t)b * SS * UU);
        float4* dst = reinterpret_cast<float4*>(enc_sh);
        for (int i = tid; i < SS * UU / 4; i += 256) dst[i] = src[i];
    }
    __syncthreads();
    for (int i = tid; i < UU; i += 256) h_sh[i] = enc_sh[(SS - 1) * UU + i];
    __syncthreads();

    const float* Pb = P + (size_t)b * SS * G3;

    for (int t = 0; t < TD; t++) {
        {
            float acc[5] = {0.f, 0.f, 0.f, 0.f, 0.f};
#pragma unroll 4
            for (int i = 0; i < 32; i++) {
                int uidx = lane + 32 * i;
                float hv = h_sh[uidx];
#pragma unroll
                for (int q = 0; q < 5; q++)
                    acc[q] += hv * enc_sh[(warp * 5 + q) * UU + uidx];
            }
#pragma unroll
            for (int q = 0; q < 5; q++) {
                float v = acc[q];
                for (int o = 16; o; o >>= 1) v += __shfl_xor_sync(0xffffffffu, v, o);
                if (lane == 0) wsm[warp * 5 + q] = v;
            }
        }
        __syncthreads();

        if (tid == 0) {
            float mx = -1e30f;
            for (int s = 0; s < SS; s++) mx = fmaxf(mx, wsm[s]);
            float smv = 0.f;
            for (int s = 0; s < SS; s++) { float e = expf(wsm[s] - mx); wsm[s] = e; smv += e; }
            float inv = 1.f / smv;
            for (int s = 0; s < SS; s++) wsm[s] *= inv;
        }
        __syncthreads();

        {
            float a[12];
#pragma unroll
            for (int i = 0; i < 12; i++) a[i] = 0.f;
            for (int s = 0; s < SS; s++) {
                float w = wsm[s];
                const float* row = Pb + (size_t)s * G3;
#pragma unroll
                for (int i = 0; i < 12; i++)
                    a[i] += w * row[tid + i * 256];
            }
#pragma unroll
            for (int i = 0; i < 12; i++) gxc[tid + i * 256] = a[i];
        }
        __syncthreads();

        {
            const float* gx = gxd + (size_t)(b * TD + t) * G3;
            float* ho = hdec + (size_t)(b * TD + t) * UU;
#pragma unroll
            for (int i = 0; i < 4; i++) {
                int u = tid + i * 256;
                float z = sigmoidf_(gxc[u] + gx[u] + db1[u]);
                float r = sigmoidf_(gxc[UU + u] + gx[UU + u] + db1[UU + u]);
                float c = tanhf(gxc[2 * UU + u] + gx[2 * UU + u] + r * db1[2 * UU + u]);
                float hn = (1.f - z) * c;
                h_sh[u] = hn;
                ho[u] = hn;
            }
        }
        __syncthreads();
    }
}

// ---------------------------------------------------------------------------
extern "C" void kernel_launch(void* const* d_in, const int* in_sizes, int n_in,
                              void* d_out, int out_size)
{
    const int*   inp     = (const int*)d_in[0];
    const int*   targ    = (const int*)d_in[1];
    const float* enc_emb = (const float*)d_in[2];
    const float* enc_Wx  = (const float*)d_in[3];
    const float* enc_Wh  = (const float*)d_in[4];
    const float* enc_b   = (const float*)d_in[5];
    const float* dec_emb = (const float*)d_in[6];
    const float* dec_Wx  = (const float*)d_in[7];
    // d_in[8] = dec_Wh: provably unused (decoder GRU hidden input is zeros)
    const float* dec_b   = (const float*)d_in[9];
    const float* fc_W    = (const float*)d_in[10];
    const float* fc_b    = (const float*)d_in[11];
    float* out = (float*)d_out;

    float *gxe, *gxd, *enc_out, *P, *hdec;
    unsigned* bar;
    cudaGetSymbolAddress((void**)&gxe,     g_gxe);
    cudaGetSymbolAddress((void**)&gxd,     g_gxd);
    cudaGetSymbolAddress((void**)&enc_out, g_enc_out);
    cudaGetSymbolAddress((void**)&P,       g_P);
    cudaGetSymbolAddress((void**)&hdec,    g_hdec);
    cudaGetSymbolAddress((void**)&bar,     g_bar);

    cudaFuncSetAttribute(enc_persistent,
                         cudaFuncAttributeMaxDynamicSharedMemorySize, ENC_SMEM_BYTES);
    cudaFuncSetAttribute(dec_persistent,
                         cudaFuncAttributeMaxDynamicSharedMemorySize, DEC_SMEM_BYTES);

    // 1) Encoder gx (fp32 — feeds the recurrence, keep full precision)
    gemm_f32<<<dim3(G3 / 128, (BB * SS + 127) / 128), 256>>>(
        nullptr, enc_emb, inp, SS, SS, EE,
        enc_Wx, G3, enc_b, gxe, BB * SS, G3, EE);

    // 2) Decoder xt-part gx (tf32 tensor path)
    gemm_tf32<<<dim3(G3 / 128, (BB * TD + 127) / 128), 256>>>(
        nullptr, dec_emb, targ, TD, SS, EE,
        dec_Wx + (size_t)UU * G3, G3, dec_b, gxd, BB * TD, G3, EE);

    // 3) Encoder recurrence: persistent TENSOR kernel (Dekker-split tf32)
    enc_persistent<<<ENC_BLOCKS, ENC_THREADS, ENC_SMEM_BYTES>>>(
        gxe, enc_Wh, enc_b + G3, enc_out, bar, bar + 1);

    // 4) P = enc_out @ dec_Wx[:U]   (tf32 tensor path)
    gemm_tf32<<<dim3(G3 / 128, (BB * SS + 127) / 128), 256>>>(
        enc_out, nullptr, nullptr, 1, 1, UU,
        dec_Wx, G3, nullptr, P, BB * SS, G3, UU);

    // 5) Decoder recurrence: ONE persistent kernel (batch-parallel)
    dec_persistent<<<BB, 256, DEC_SMEM_BYTES>>>(
        enc_out, P, gxd, dec_b + G3, hdec);

    // 6) Batched output projection (tf32 tensor path)
    gemm_tf32<<<dim3(VV / 128, (BB * TD + 127) / 128), 256>>>(
        hdec, nullptr, nullptr, 1, 1, UU,
        fc_W, VV, fc_b, out, BB * TD, VV, UU);
}